// round 10
// baseline (speedup 1.0000x reference)
#include <cuda_runtime.h>
#include <cuda_bf16.h>
#include <math.h>
#include <stdint.h>

#define BATCH 512
#define SEQ   201
#define EMBD  128
#define NHEAD 4
#define HDIM  32
#define FFD   256
#define NEXP  5
#define NLAYER 6
#define NTOK  (BATCH*SEQ)          // 102912

typedef __nv_bfloat16 bf16;

// ---------------- scratch (device globals; no runtime allocation) ----------
__device__ float g_x   [(size_t)NTOK*EMBD];
__device__ float g_qkv [(size_t)NTOK*3*EMBD];
__device__ float g_gate[(size_t)NTOK*NEXP];
__device__ bf16  g_hh  [(size_t)NTOK*EMBD];
__device__ bf16  g_hl  [(size_t)NTOK*EMBD];
__device__ bf16  g_oh  [(size_t)NTOK*EMBD];
__device__ bf16  g_ol  [(size_t)NTOK*EMBD];
__device__ bf16  g_hidh[(size_t)NTOK*NEXP*FFD];
__device__ bf16  g_hidl[(size_t)NTOK*NEXP*FFD];
// weight planes
__device__ bf16  g_wqkvh[(size_t)NLAYER*3*EMBD*EMBD], g_wqkvl[(size_t)NLAYER*3*EMBD*EMBD];
__device__ bf16  g_woh  [(size_t)NLAYER*EMBD*EMBD],   g_wol  [(size_t)NLAYER*EMBD*EMBD];
__device__ bf16  g_w1h  [(size_t)NLAYER*NEXP*FFD*EMBD], g_w1l[(size_t)NLAYER*NEXP*FFD*EMBD];
__device__ bf16  g_w2h  [(size_t)NLAYER*EMBD*NEXP*FFD], g_w2l[(size_t)NLAYER*EMBD*NEXP*FFD];

// ---------------- helpers -----------------------------------------------------
__device__ __forceinline__ void split2(float x, float y, uint32_t& hi, uint32_t& lo) {
    __nv_bfloat162 h, l;
    h.x = __float2bfloat16(x); h.y = __float2bfloat16(y);
    l.x = __float2bfloat16(x - __bfloat162float(h.x));
    l.y = __float2bfloat16(y - __bfloat162float(h.y));
    hi = *(uint32_t*)&h; lo = *(uint32_t*)&l;
}

#define MMA_BF16(d, a, b0, b1)                                                   \
    asm volatile("mma.sync.aligned.m16n8k16.row.col.f32.bf16.bf16.f32 "          \
                 "{%0,%1,%2,%3},{%4,%5,%6,%7},{%8,%9},{%0,%1,%2,%3};"            \
                 : "+f"(d[0]), "+f"(d[1]), "+f"(d[2]), "+f"(d[3])                 \
                 : "r"(a[0]), "r"(a[1]), "r"(a[2]), "r"(a[3]), "r"(b0), "r"(b1))

#define CP_ASYNC16(saddr, gaddr)                                                  \
    asm volatile("cp.async.cg.shared.global [%0], [%1], 16;" :: "r"(saddr), "l"(gaddr))

#define LDSM_X4(r0, r1, r2, r3, addr)                                             \
    asm volatile("ldmatrix.sync.aligned.m8n8.x4.shared.b16 {%0,%1,%2,%3}, [%4];"  \
                 : "=r"(r0), "=r"(r1), "=r"(r2), "=r"(r3) : "r"(addr))

#define LDSM_X2(r0, r1, addr)                                                     \
    asm volatile("ldmatrix.sync.aligned.m8n8.x2.shared.b16 {%0,%1}, [%2];"        \
                 : "=r"(r0), "=r"(r1) : "r"(addr))

// ---------------- weight prep -------------------------------------------------
__global__ void split_two(const float* __restrict__ a, bf16* __restrict__ ah,
                          bf16* __restrict__ al, int na,
                          const float* __restrict__ b, bf16* __restrict__ bh,
                          bf16* __restrict__ bl, int nb)
{
    int i = blockIdx.x*256 + threadIdx.x;
    if (i < na) {
        float v = a[i];
        bf16 h = __float2bfloat16(v);
        ah[i] = h;
        al[i] = __float2bfloat16(v - __bfloat162float(h));
    } else if (i - na < nb) {
        int j = i - na;
        float v = b[j];
        bf16 h = __float2bfloat16(v);
        bh[j] = h;
        bl[j] = __float2bfloat16(v - __bfloat162float(h));
    }
}

__global__ void trans_split(const float* __restrict__ in, bf16* __restrict__ oh,
                            bf16* __restrict__ ol, int R, int C)
{
    __shared__ float tile[32][33];
    int mat = blockIdx.z;
    const float* src = in + (size_t)mat*R*C;
    int c0 = blockIdx.x*32, r0 = blockIdx.y*32;
    int x = threadIdx.x, y = threadIdx.y;
    #pragma unroll
    for (int i = 0; i < 32; i += 8)
        tile[y+i][x] = src[(size_t)(r0+y+i)*C + c0+x];
    __syncthreads();
    #pragma unroll
    for (int i = 0; i < 32; i += 8) {
        float v = tile[x][y+i];
        size_t idx = (size_t)mat*R*C + (size_t)(c0+y+i)*R + r0+x;
        bf16 h = __float2bfloat16(v);
        oh[idx] = h;
        ol[idx] = __float2bfloat16(v - __bfloat162float(h));
    }
}

// ---------------- embed + LN0 ----------------------------------------------
__global__ void embed_ln0_kernel(const int* __restrict__ x_cat,
                                 const float* __restrict__ x_num,
                                 const float* __restrict__ x_eng,
                                 const float* __restrict__ emb,
                                 const float* __restrict__ emb_bias,
                                 const float* __restrict__ emb_eng,
                                 const float* __restrict__ emb_bias_eng,
                                 const float* __restrict__ w,
                                 const float* __restrict__ bb,
                                 float* __restrict__ xout)
{
    int tok = blockIdx.x;
    int b = tok / SEQ, t = tok % SEQ;
    int j = threadIdx.x;

    float v;
    if (t < 53) {
        int idx = x_cat[(b*51 + 50)*53 + t];
        v = emb[(size_t)idx*EMBD + j] + emb_bias[t*EMBD + j];
    } else if (t < 100) {
        int c = t - 53;
        v = emb[(size_t)(1306 + c)*EMBD + j] * x_num[(b*51 + 50)*47 + c]
            + emb_bias[t*EMBD + j];
    } else if (t < 200) {
        int c = t - 100;
        v = emb_eng[c*EMBD + j] * x_eng[b*100 + c] + emb_bias_eng[c*EMBD + j];
    } else {
        v = 0.f;
    }

    __shared__ float red[8];
    int lane = j & 31, warp = j >> 5;
    float s = v;
    #pragma unroll
    for (int o = 16; o; o >>= 1) s += __shfl_xor_sync(0xffffffffu, s, o);
    if (lane == 0) red[warp] = s;
    __syncthreads();
    float m = (red[0] + red[1] + red[2] + red[3]) * (1.f/128.f);
    float d = v - m;
    float s2 = d * d;
    #pragma unroll
    for (int o = 16; o; o >>= 1) s2 += __shfl_xor_sync(0xffffffffu, s2, o);
    if (lane == 0) red[4 + warp] = s2;
    __syncthreads();
    float var = (red[4] + red[5] + red[6] + red[7]) * (1.f/128.f);
    xout[(size_t)tok*EMBD + j] = d * rsqrtf(var + 1e-5f) * w[j] + bb[j];
}

// ---------------- warp-per-token LayerNorm -> bf16 hi/lo planes ---------------
__global__ void ln_warp_p(const float* __restrict__ src,
                          bf16* __restrict__ dh, bf16* __restrict__ dl,
                          const float* __restrict__ w, const float* __restrict__ bb,
                          int t0, int tstride)
{
    int lane = threadIdx.x & 31;
    int tokl = blockIdx.x * (blockDim.x >> 5) + (threadIdx.x >> 5);
    size_t tok = (size_t)t0 + (size_t)tokl * tstride;

    float4 v = *(const float4*)(src + tok*EMBD + lane*4);
    float s = v.x + v.y + v.z + v.w;
    #pragma unroll
    for (int o = 16; o; o >>= 1) s += __shfl_xor_sync(0xffffffffu, s, o);
    float m = s * (1.f/128.f);
    float dx = v.x-m, dy = v.y-m, dz = v.z-m, dw = v.w-m;
    float s2 = dx*dx + dy*dy + dz*dz + dw*dw;
    #pragma unroll
    for (int o = 16; o; o >>= 1) s2 += __shfl_xor_sync(0xffffffffu, s2, o);
    float inv = rsqrtf(s2 * (1.f/128.f) + 1e-5f);
    float4 wv = *(const float4*)(w + lane*4);
    float4 bv = *(const float4*)(bb + lane*4);
    float r0 = dx*inv*wv.x + bv.x, r1 = dy*inv*wv.y + bv.y;
    float r2 = dz*inv*wv.z + bv.z, r3 = dw*inv*wv.w + bv.w;
    uint32_t h0,l0,h1,l1;
    split2(r0, r1, h0, l0); split2(r2, r3, h1, l1);
    uint32_t* ph = (uint32_t*)(dh + tok*EMBD + lane*4);
    uint32_t* pl = (uint32_t*)(dl + tok*EMBD + lane*4);
    ph[0] = h0; ph[1] = h1; pl[0] = l0; pl[1] = l1;
}

// ---------------- fused LN2 + gate softmax -> planes --------------------------
__global__ void ln2g_p(const float* __restrict__ src,
                       bf16* __restrict__ dh, bf16* __restrict__ dl,
                       const float* __restrict__ w, const float* __restrict__ bb,
                       const float* __restrict__ Wg, const float* __restrict__ bg,
                       float* __restrict__ gate, int t0, int tstride)
{
    int lane = threadIdx.x & 31;
    int tokl = blockIdx.x * (blockDim.x >> 5) + (threadIdx.x >> 5);
    size_t tok = (size_t)t0 + (size_t)tokl * tstride;

    float4 v = *(const float4*)(src + tok*EMBD + lane*4);
    float s = v.x + v.y + v.z + v.w;
    #pragma unroll
    for (int o = 16; o; o >>= 1) s += __shfl_xor_sync(0xffffffffu, s, o);
    float m = s * (1.f/128.f);
    float dx = v.x-m, dy = v.y-m, dz = v.z-m, dw = v.w-m;
    float s2 = dx*dx + dy*dy + dz*dz + dw*dw;
    #pragma unroll
    for (int o = 16; o; o >>= 1) s2 += __shfl_xor_sync(0xffffffffu, s2, o);
    float inv = rsqrtf(s2 * (1.f/128.f) + 1e-5f);
    float4 wv = *(const float4*)(w + lane*4);
    float4 bv = *(const float4*)(bb + lane*4);
    float h[4];
    h[0] = dx*inv*wv.x + bv.x; h[1] = dy*inv*wv.y + bv.y;
    h[2] = dz*inv*wv.z + bv.z; h[3] = dw*inv*wv.w + bv.w;
    uint32_t hh0,ll0,hh1,ll1;
    split2(h[0], h[1], hh0, ll0); split2(h[2], h[3], hh1, ll1);
    uint32_t* ph = (uint32_t*)(dh + tok*EMBD + lane*4);
    uint32_t* pl = (uint32_t*)(dl + tok*EMBD + lane*4);
    ph[0] = hh0; ph[1] = hh1; pl[0] = ll0; pl[1] = ll1;

    float p[NEXP];
    #pragma unroll
    for (int e = 0; e < NEXP; e++) p[e] = 0.f;
    #pragma unroll
    for (int q = 0; q < 4; q++) {
        int j = lane*4 + q;
        #pragma unroll
        for (int e = 0; e < NEXP; e++) p[e] += h[q] * Wg[j*NEXP + e];
    }
    #pragma unroll
    for (int e = 0; e < NEXP; e++)
        #pragma unroll
        for (int o = 16; o; o >>= 1) p[e] += __shfl_xor_sync(0xffffffffu, p[e], o);
    if (lane == 0) {
        float mx = -1e30f;
        #pragma unroll
        for (int e = 0; e < NEXP; e++) { p[e] += bg[e]; mx = fmaxf(mx, p[e]); }
        float sum = 0.f;
        #pragma unroll
        for (int e = 0; e < NEXP; e++) { p[e] = __expf(p[e] - mx); sum += p[e]; }
        float is = 1.f / sum;
        #pragma unroll
        for (int e = 0; e < NEXP; e++) gate[tok*NEXP + e] = p[e] * is;
    }
}

// ---------------- bf16x3 GEMM: M=64 CTA tile, 3 CTAs/SM -----------------------
// C[M,N] = A @ B^T ; A planes [M][K], B planes [N][K].
// 256 threads, CTA tile 64x128, 8 warps of 32x32, 3-stage cp.async, ldmatrix.
// EPI 0: C = acc+bias ; EPI 1: planes = split(relu(acc+bias)*gate[m][bx>>1])
// EPI 3: C += acc+bias ; EPI 4: C += acc + sum_e gate[m][e]*bias[e*128+n]
#define GEMM_KP   24
#define GEMM_APL  (64*GEMM_KP)     // 1536 elems
#define GEMM_BPL  (128*GEMM_KP)    // 3072 elems
#define GEMM_SMEM ((2*3*GEMM_APL + 2*3*GEMM_BPL)*2)   // 55296 bytes

template<int EPI>
__global__ void __launch_bounds__(256, 3)
gemm_p(const bf16* __restrict__ Ahp, const bf16* __restrict__ Alp, long rsA,
       const bf16* __restrict__ Bhp, const bf16* __restrict__ Blp,
       const float* __restrict__ bias,
       float* __restrict__ C, long rsC,
       bf16* __restrict__ Chp, bf16* __restrict__ Clp,
       const float* __restrict__ gate, long rsG,
       int K)
{
    constexpr int KP = GEMM_KP;
    constexpr int APL = GEMM_APL;
    constexpr int BPL = GEMM_BPL;
    extern __shared__ bf16 smg[];
    bf16* Ah = smg;
    bf16* Al = Ah + 3*APL;
    bf16* Bh = Al + 3*APL;
    bf16* Bl = Bh + 3*BPL;

    const int tid  = threadIdx.x;
    const int warp = tid >> 5, lane = tid & 31;
    const int g = lane >> 2, r = lane & 3;
    const int wm = (warp & 1) * 32;     // 2 warps along M (64)
    const int wn = (warp >> 1) * 32;    // 4 warps along N (128)
    const int bx = blockIdx.x, by = blockIdx.y;

    float c[2][4][4];
    #pragma unroll
    for (int mi = 0; mi < 2; mi++)
        #pragma unroll
        for (int ni = 0; ni < 4; ni++)
            #pragma unroll
            for (int q = 0; q < 4; q++) c[mi][ni][q] = 0.f;

    // cp.async staging: B by all 256 threads, A by tid<128
    const int srow = tid >> 1;
    const int sseg = (tid & 1) << 3;
    const bf16* gAh = Ahp + (size_t)(by*64 + srow)*rsA + sseg;   // valid for tid<128
    const bf16* gAl = Alp + (size_t)(by*64 + srow)*rsA + sseg;
    const bf16* gBh = Bhp + (size_t)(bx*128 + srow)*K + sseg;
    const bf16* gBl = Blp + (size_t)(bx*128 + srow)*K + sseg;

    uint32_t baseAh = (uint32_t)__cvta_generic_to_shared(Ah);
    uint32_t baseAl = (uint32_t)__cvta_generic_to_shared(Al);
    uint32_t baseBh = (uint32_t)__cvta_generic_to_shared(Bh);
    uint32_t baseBl = (uint32_t)__cvta_generic_to_shared(Bl);

    auto stage = [&](int k0, int s) {
        if (tid < 128) {
            uint32_t offA = (uint32_t)(s*APL + srow*KP + sseg) * 2;
            CP_ASYNC16(baseAh + offA, gAh + k0);
            CP_ASYNC16(baseAl + offA, gAl + k0);
        }
        uint32_t offB = (uint32_t)(s*BPL + srow*KP + sseg) * 2;
        CP_ASYNC16(baseBh + offB, gBh + k0);
        CP_ASYNC16(baseBl + offB, gBl + k0);
        asm volatile("cp.async.commit_group;" ::: "memory");
    };

    // ldmatrix lane offsets (bytes within a stage)
    uint32_t a_off[2];
    #pragma unroll
    for (int mi = 0; mi < 2; mi++)
        a_off[mi] = (uint32_t)(((wm + mi*16 + (lane & 15))*KP + ((lane >> 4) << 3)) * 2);
    uint32_t b_off[2];
    #pragma unroll
    for (int p = 0; p < 2; p++)
        b_off[p] = (uint32_t)(((wn + p*16 + (lane & 7) + ((lane >> 4) << 3))*KP
                               + (((lane >> 3) & 1) << 3)) * 2);

    auto compute = [&](int s) {
        uint32_t soA = (uint32_t)(s*APL*2);
        uint32_t soB = (uint32_t)(s*BPL*2);
        uint32_t ah[2][4], al[2][4];
        #pragma unroll
        for (int mi = 0; mi < 2; mi++) {
            LDSM_X4(ah[mi][0], ah[mi][1], ah[mi][2], ah[mi][3], baseAh + soA + a_off[mi]);
            LDSM_X4(al[mi][0], al[mi][1], al[mi][2], al[mi][3], baseAl + soA + a_off[mi]);
        }
        #pragma unroll
        for (int p = 0; p < 2; p++) {
            uint32_t bh[4], bl[4];
            LDSM_X4(bh[0], bh[1], bh[2], bh[3], baseBh + soB + b_off[p]);
            LDSM_X4(bl[0], bl[1], bl[2], bl[3], baseBl + soB + b_off[p]);
            // per-accumulator order hh, lh, hl (reuse distance 4)
            MMA_BF16(c[0][2*p],   ah[0], bh[0], bh[1]);
            MMA_BF16(c[1][2*p],   ah[1], bh[0], bh[1]);
            MMA_BF16(c[0][2*p+1], ah[0], bh[2], bh[3]);
            MMA_BF16(c[1][2*p+1], ah[1], bh[2], bh[3]);
            MMA_BF16(c[0][2*p],   al[0], bh[0], bh[1]);
            MMA_BF16(c[1][2*p],   al[1], bh[0], bh[1]);
            MMA_BF16(c[0][2*p+1], al[0], bh[2], bh[3]);
            MMA_BF16(c[1][2*p+1], al[1], bh[2], bh[3]);
            MMA_BF16(c[0][2*p],   ah[0], bl[0], bl[1]);
            MMA_BF16(c[1][2*p],   ah[1], bl[0], bl[1]);
            MMA_BF16(c[0][2*p+1], ah[0], bl[2], bl[3]);
            MMA_BF16(c[1][2*p+1], ah[1], bl[2], bl[3]);
        }
    };

    const int nk = K >> 4;
    stage(0, 0);
    if (nk > 1) stage(16, 1);
    for (int it = 0; it < nk; ++it) {
        if (it + 1 < nk) asm volatile("cp.async.wait_group 1;" ::: "memory");
        else             asm volatile("cp.async.wait_group 0;" ::: "memory");
        __syncthreads();
        compute(it % 3);
        if (it + 2 < nk) stage((it + 2) << 4, (it + 2) % 3);
    }

    // ---------------- epilogue ----------------
    if (EPI == 4) {
        #pragma unroll
        for (int mi = 0; mi < 2; mi++)
            #pragma unroll
            for (int half = 0; half < 2; half++) {
                int m = by*64 + wm + mi*16 + g + half*8;
                float gg[NEXP];
                #pragma unroll
                for (int e = 0; e < NEXP; e++) gg[e] = gate[(size_t)m*rsG + e];
                float* crow2 = C + (size_t)m*rsC;
                #pragma unroll
                for (int ni = 0; ni < 4; ni++) {
                    int col = wn + ni*8 + 2*r;
                    float a0 = 0.f, a1 = 0.f;
                    #pragma unroll
                    for (int e = 0; e < NEXP; e++) {
                        a0 += gg[e] * bias[e*128 + col];
                        a1 += gg[e] * bias[e*128 + col + 1];
                    }
                    float2 old = *(float2*)(crow2 + col);
                    old.x += c[mi][ni][half*2 + 0] + a0;
                    old.y += c[mi][ni][half*2 + 1] + a1;
                    *(float2*)(crow2 + col) = old;
                }
            }
    } else if (EPI == 1) {
        #pragma unroll
        for (int mi = 0; mi < 2; mi++)
            #pragma unroll
            for (int half = 0; half < 2; half++) {
                int m = by*64 + wm + mi*16 + g + half*8;
                float gv = gate[(size_t)m*rsG + (bx >> 1)];
                #pragma unroll
                for (int ni = 0; ni < 4; ni++) {
                    int n = wn + ni*8 + 2*r;
                    float v0 = fmaxf(c[mi][ni][half*2+0] + bias[bx*128 + n],   0.f) * gv;
                    float v1 = fmaxf(c[mi][ni][half*2+1] + bias[bx*128 + n+1], 0.f) * gv;
                    uint32_t hi, lo;
                    split2(v0, v1, hi, lo);
                    *(uint32_t*)(Chp + (size_t)m*rsC + bx*128 + n) = hi;
                    *(uint32_t*)(Clp + (size_t)m*rsC + bx*128 + n) = lo;
                }
            }
    } else {
        #pragma unroll
        for (int mi = 0; mi < 2; mi++)
            #pragma unroll
            for (int half = 0; half < 2; half++) {
                int m = by*64 + wm + mi*16 + g + half*8;
                float* crow2 = C + (size_t)m*rsC + bx*128;
                const float* brow = bias + bx*128;
                #pragma unroll
                for (int ni = 0; ni < 4; ni++) {
                    int n = wn + ni*8 + 2*r;
                    float v0 = c[mi][ni][half*2 + 0] + brow[n];
                    float v1 = c[mi][ni][half*2 + 1] + brow[n+1];
                    if (EPI == 0) {
                        *(float2*)(crow2 + n) = make_float2(v0, v1);
                    } else {
                        float2 old = *(float2*)(crow2 + n);
                        old.x += v0; old.y += v1;
                        *(float2*)(crow2 + n) = old;
                    }
                }
            }
    }
}

// ---------------- mma attention ------------------------------------------------
#define KSTR 40
#define VSTR 216
#define PSTR 232
#define ATTN_SMEM (208*KSTR*2*2 + 32*VSTR*2*2 + 32*PSTR*2*2 + 2*8*32*4)  // 92672

__global__ void __launch_bounds__(256, 2)
attn_mma(const float* __restrict__ qkv, bf16* __restrict__ ohi, bf16* __restrict__ olo,
         int q0)
{
    extern __shared__ char smraw[];
    bf16* Kh = (bf16*)smraw;                 // [208][KSTR]
    bf16* Kl = Kh + 208*KSTR;
    bf16* Vh = Kl + 208*KSTR;                // [32][VSTR]  (V transposed: [d][key])
    bf16* Vl = Vh + 32*VSTR;
    bf16* Ph = Vl + 32*VSTR;                 // [32][PSTR]
    bf16* Pl = Ph + 32*PSTR;
    float* wmax = (float*)(Pl + 32*PSTR);    // [32 rows][8 warps]
    float* wsum = wmax + 256;

    const int bh0_ = blockIdx.x, b = bh0_ >> 2, h = bh0_ & 3;
    const float* base = qkv + (size_t)b*SEQ*(3*EMBD) + h*HDIM;
    const int tid = threadIdx.x, warp = tid >> 5, lane = tid & 31;
    const int g = lane >> 2, r = lane & 3;
    const float scale = 0.1767766952966369f;   // 1/sqrt(32)

    uint32_t baseKh = (uint32_t)__cvta_generic_to_shared(Kh);
    uint32_t baseKl = (uint32_t)__cvta_generic_to_shared(Kl);
    uint32_t baseVh = (uint32_t)__cvta_generic_to_shared(Vh);
    uint32_t baseVl = (uint32_t)__cvta_generic_to_shared(Vl);
    uint32_t basePh = (uint32_t)__cvta_generic_to_shared(Ph);
    uint32_t basePl = (uint32_t)__cvta_generic_to_shared(Pl);

    for (int idx = tid; idx < 208*32; idx += 256) {
        int t = idx >> 5, d = idx & 31;
        float kv = 0.f, vv = 0.f;
        if (t < SEQ) {
            kv = base[(size_t)t*(3*EMBD) + EMBD   + d];
            vv = base[(size_t)t*(3*EMBD) + 2*EMBD + d];
        }
        bf16 khv = __float2bfloat16(kv);
        Kh[t*KSTR + d] = khv;
        Kl[t*KSTR + d] = __float2bfloat16(kv - __bfloat162float(khv));
        bf16 vhv = __float2bfloat16(vv);
        Vh[d*VSTR + t] = vhv;
        Vl[d*VSTR + t] = __float2bfloat16(vv - __bfloat162float(vhv));
    }
    __syncthreads();

    const uint32_t kofl = (uint32_t)((((lane & 7))*KSTR + (((lane >> 3) & 3) << 3)) * 2);
    const uint32_t pofl = (uint32_t)(((lane & 15))*PSTR*2 + (((lane >> 4) << 3)) * 2);
    const uint32_t vofl = (uint32_t)((((lane & 7))*VSTR + (((lane >> 3) & 1) << 3)) * 2);

    for (int qt = q0; qt < SEQ; qt += 32) {
        uint32_t qh[2][2][4], ql[2][2][4];
        #pragma unroll
        for (int mi = 0; mi < 2; mi++)
            #pragma unroll
            for (int ks = 0; ks < 2; ks++)
                #pragma unroll
                for (int j = 0; j < 4; j++) {
                    int qq = qt + mi*16 + g + (j & 1)*8;
                    if (qq > 200) qq = 200;
                    int kk = ks*16 + 2*r + (j >> 1)*8;
                    float2 v = *(const float2*)(base + (size_t)qq*(3*EMBD) + kk);
                    split2(v.x*scale, v.y*scale, qh[mi][ks][j], ql[mi][ks][j]);
                }

        float sc[4][2][4];
        #pragma unroll
        for (int ti = 0; ti < 4; ti++)
            #pragma unroll
            for (int mi = 0; mi < 2; mi++)
                #pragma unroll
                for (int q = 0; q < 4; q++) sc[ti][mi][q] = 0.f;

        #pragma unroll
        for (int ti = 0; ti < 4; ti++) {
            int t = warp + ti*8;
            if (t < 26) {
                uint32_t ko = (uint32_t)(t*8*KSTR*2) + kofl;
                uint32_t bhv[4], blv[4];
                LDSM_X4(bhv[0], bhv[1], bhv[2], bhv[3], baseKh + ko);
                LDSM_X4(blv[0], blv[1], blv[2], blv[3], baseKl + ko);
                MMA_BF16(sc[ti][0], qh[0][0], bhv[0], bhv[1]);
                MMA_BF16(sc[ti][1], qh[1][0], bhv[0], bhv[1]);
                MMA_BF16(sc[ti][0], ql[0][0], bhv[0], bhv[1]);
                MMA_BF16(sc[ti][1], ql[1][0], bhv[0], bhv[1]);
                MMA_BF16(sc[ti][0], qh[0][0], blv[0], blv[1]);
                MMA_BF16(sc[ti][1], qh[1][0], blv[0], blv[1]);
                MMA_BF16(sc[ti][0], qh[0][1], bhv[2], bhv[3]);
                MMA_BF16(sc[ti][1], qh[1][1], bhv[2], bhv[3]);
                MMA_BF16(sc[ti][0], ql[0][1], bhv[2], bhv[3]);
                MMA_BF16(sc[ti][1], ql[1][1], bhv[2], bhv[3]);
                MMA_BF16(sc[ti][0], qh[0][1], blv[2], blv[3]);
                MMA_BF16(sc[ti][1], qh[1][1], blv[2], blv[3]);
            }
        }

        float gm[2][2], gs[2][2];
        #pragma unroll
        for (int mi = 0; mi < 2; mi++)
            #pragma unroll
            for (int h2 = 0; h2 < 2; h2++) {
                float mx = -1e30f;
                #pragma unroll
                for (int ti = 0; ti < 4; ti++) {
                    int t = warp + ti*8;
                    if (t < 26) {
                        int c0 = t*8 + 2*r;
                        if (c0     <= 200) mx = fmaxf(mx, sc[ti][mi][h2*2+0]);
                        if (c0 + 1 <= 200) mx = fmaxf(mx, sc[ti][mi][h2*2+1]);
                    }
                }
                mx = fmaxf(mx, __shfl_xor_sync(0xffffffffu, mx, 1));
                mx = fmaxf(mx, __shfl_xor_sync(0xffffffffu, mx, 2));
                if (r == 0) wmax[(mi*16 + g + h2*8)*8 + warp] = mx;
            }
        __syncthreads();
        #pragma unroll
        for (int mi = 0; mi < 2; mi++)
            #pragma unroll
            for (int h2 = 0; h2 < 2; h2++) {
                int row = mi*16 + g + h2*8;
                float mx = wmax[row*8];
                #pragma unroll
                for (int w2 = 1; w2 < 8; w2++) mx = fmaxf(mx, wmax[row*8 + w2]);
                gm[mi][h2] = mx;
            }
        #pragma unroll
        for (int mi = 0; mi < 2; mi++)
            #pragma unroll
            for (int h2 = 0; h2 < 2; h2++) {
                float s = 0.f;
                #pragma unroll
                for (int ti = 0; ti < 4; ti++) {
                    int t = warp + ti*8;
                    if (t < 26) {
                        int c0 = t*8 + 2*r;
                        float p0 = (c0     <= 200) ? __expf(sc[ti][mi][h2*2+0] - gm[mi][h2]) : 0.f;
                        float p1 = (c0 + 1 <= 200) ? __expf(sc[ti][mi][h2*2+1] - gm[mi][h2]) : 0.f;
                        sc[ti][mi][h2*2+0] = p0; sc[ti][mi][h2*2+1] = p1;
                        s += p0 + p1;
                    }
                }
                s += __shfl_xor_sync(0xffffffffu, s, 1);
                s += __shfl_xor_sync(0xffffffffu, s, 2);
                if (r == 0) wsum[(mi*16 + g + h2*8)*8 + warp] = s;
            }
        __syncthreads();
        #pragma unroll
        for (int mi = 0; mi < 2; mi++)
            #pragma unroll
            for (int h2 = 0; h2 < 2; h2++) {
                int row = mi*16 + g + h2*8;
                float s = 0.f;
                #pragma unroll
                for (int w2 = 0; w2 < 8; w2++) s += wsum[row*8 + w2];
                gs[mi][h2] = 1.f / s;
            }
        #pragma unroll
        for (int ti = 0; ti < 4; ti++) {
            int t = warp + ti*8;
            if (t < 26) {
                int c0 = t*8 + 2*r;
                #pragma unroll
                for (int mi = 0; mi < 2; mi++)
                    #pragma unroll
                    for (int h2 = 0; h2 < 2; h2++) {
                        int row = mi*16 + g + h2*8;
                        uint32_t hi, lo;
                        split2(sc[ti][mi][h2*2+0]*gs[mi][h2],
                               sc[ti][mi][h2*2+1]*gs[mi][h2], hi, lo);
                        *(uint32_t*)(Ph + row*PSTR + c0) = hi;
                        *(uint32_t*)(Pl + row*PSTR + c0) = lo;
                    }
            }
        }
        __syncthreads();

        {
            int mi = warp >> 2, ni = warp & 3;
            float oc[4] = {0.f, 0.f, 0.f, 0.f};
            #pragma unroll
            for (int ks = 0; ks < 13; ks++) {
                uint32_t po = (uint32_t)((mi*16*PSTR + ks*16) * 2) + pofl;
                uint32_t ah[4], al[4];
                LDSM_X4(ah[0], ah[1], ah[2], ah[3], basePh + po);
                LDSM_X4(al[0], al[1], al[2], al[3], basePl + po);
                uint32_t vo = (uint32_t)((ni*8*VSTR + ks*16) * 2) + vofl;
                uint32_t bh0, bh1, bl0, bl1;
                LDSM_X2(bh0, bh1, baseVh + vo);
                LDSM_X2(bl0, bl1, baseVl + vo);
                MMA_BF16(oc, ah, bh0, bh1);
                MMA_BF16(oc, al, bh0, bh1);
                MMA_BF16(oc, ah, bl0, bl1);
            }
            #pragma unroll
            for (int h2 = 0; h2 < 2; h2++) {
                int q = qt + mi*16 + g + h2*8;
                if (q <= 200) {
                    int d = ni*8 + 2*r;
                    uint32_t hi, lo;
                    split2(oc[h2*2+0], oc[h2*2+1], hi, lo);
                    size_t off = ((size_t)b*SEQ + q)*EMBD + h*HDIM + d;
                    *(uint32_t*)(ohi + off) = hi;
                    *(uint32_t*)(olo + off) = lo;
                }
            }
        }
        __syncthreads();
    }
}

// ---------------- output copy -------------------------------------------------
__global__ void copy_out_kernel(const float* __restrict__ x, float* __restrict__ out)
{
    int b = blockIdx.x, j = threadIdx.x;
    out[b*EMBD + j] = x[((size_t)b*SEQ + 200)*EMBD + j];
}

// ---------------- launcher ----------------------------------------------------
extern "C" void kernel_launch(void* const* d_in, const int* in_sizes, int n_in,
                              void* d_out, int out_size)
{
    (void)in_sizes; (void)n_in; (void)out_size;

    const int*   x_cat        = (const int*)  d_in[0];
    const float* x_num        = (const float*)d_in[1];
    const float* x_eng        = (const float*)d_in[2];
    const float* emb          = (const float*)d_in[3];
    const float* emb_bias     = (const float*)d_in[4];
    const float* emb_eng      = (const float*)d_in[5];
    const float* emb_bias_eng = (const float*)d_in[6];
    const float* ln0_w        = (const float*)d_in[7];
    const float* ln0_b        = (const float*)d_in[8];
    const float* ln1_w        = (const float*)d_in[9];
    const float* ln1_b        = (const float*)d_in[10];
    const float* Wqkv         = (const float*)d_in[11];
    const float* bqkv         = (const float*)d_in[12];
    const float* Wo           = (const float*)d_in[13];
    const float* bo           = (const float*)d_in[14];
    const float* ln2_w        = (const float*)d_in[15];
    const float* ln2_b        = (const float*)d_in[16];
    const float* Wg           = (const float*)d_in[17];
    const float* bg           = (const float*)d_in[18];
    const float* W1           = (const float*)d_in[19];
    const float* b1           = (const float*)d_in[20];
    const float* W2           = (const float*)d_in[21];
    const float* b2           = (const float*)d_in[22];
    float* out = (float*)d_out;

    float *px, *pqkv, *pgate;
    bf16 *phh, *phl, *poh, *pol, *phidh, *phidl;
    bf16 *pwqkvh, *pwqkvl, *pwoh, *pwol, *pw1h, *pw1l, *pw2h, *pw2l;
    cudaGetSymbolAddress((void**)&px,    g_x);
    cudaGetSymbolAddress((void**)&pqkv,  g_qkv);
    cudaGetSymbolAddress((void**)&pgate, g_gate);
    cudaGetSymbolAddress((void**)&phh,   g_hh);
    cudaGetSymbolAddress((void**)&phl,   g_hl);
    cudaGetSymbolAddress((void**)&poh,   g_oh);
    cudaGetSymbolAddress((void**)&pol,   g_ol);
    cudaGetSymbolAddress((void**)&phidh, g_hidh);
    cudaGetSymbolAddress((void**)&phidl, g_hidl);
    cudaGetSymbolAddress((void**)&pwqkvh, g_wqkvh);
    cudaGetSymbolAddress((void**)&pwqkvl, g_wqkvl);
    cudaGetSymbolAddress((void**)&pwoh,   g_woh);
    cudaGetSymbolAddress((void**)&pwol,   g_wol);
    cudaGetSymbolAddress((void**)&pw1h,   g_w1h);
    cudaGetSymbolAddress((void**)&pw1l,   g_w1l);
    cudaGetSymbolAddress((void**)&pw2h,   g_w2h);
    cudaGetSymbolAddress((void**)&pw2l,   g_w2l);

    cudaFuncSetAttribute(attn_mma, cudaFuncAttributeMaxDynamicSharedMemorySize, ATTN_SMEM);
    cudaFuncSetAttribute(gemm_p<0>, cudaFuncAttributeMaxDynamicSharedMemorySize, GEMM_SMEM);
    cudaFuncSetAttribute(gemm_p<1>, cudaFuncAttributeMaxDynamicSharedMemorySize, GEMM_SMEM);
    cudaFuncSetAttribute(gemm_p<3>, cudaFuncAttributeMaxDynamicSharedMemorySize, GEMM_SMEM);
    cudaFuncSetAttribute(gemm_p<4>, cudaFuncAttributeMaxDynamicSharedMemorySize, GEMM_SMEM);

    // launch order: #4 (ncu capture slot) = layer-0 QKV GEMM
    embed_ln0_kernel<<<NTOK, 128>>>(x_cat, x_num, x_eng, emb, emb_bias,
                                    emb_eng, emb_bias_eng, ln0_w, ln0_b, px);   // 1
    split_two<<<(NLAYER*4*EMBD*EMBD + 255)/256, 256>>>(
        Wqkv, pwqkvh, pwqkvl, NLAYER*3*EMBD*EMBD,
        Wo,   pwoh,   pwol,   NLAYER*EMBD*EMBD);                                 // 2
    ln_warp_p<<<NTOK/8, 256>>>(px, phh, phl, ln1_w, ln1_b, 0, 1);               // 3
    gemm_p<0><<<dim3(3, NTOK/64), 256, GEMM_SMEM>>>(phh, phl, EMBD,
                                              pwqkvh, pwqkvl, bqkv,
                                              pqkv, 3*EMBD, nullptr, nullptr,
                                              nullptr, 0, EMBD);                 // 4 (profiled)
    trans_split<<<dim3(FFD/32, EMBD/32, NLAYER*NEXP), dim3(32,8)>>>(W1, pw1h, pw1l, EMBD, FFD);
    trans_split<<<dim3(EMBD/32, (NEXP*FFD)/32, NLAYER), dim3(32,8)>>>(W2, pw2h, pw2l, NEXP*FFD, EMBD);

    for (int i = 0; i < NLAYER; i++) {
        const bf16* wqh = pwqkvh + (size_t)i*3*EMBD*EMBD;
        const bf16* wql = pwqkvl + (size_t)i*3*EMBD*EMBD;
        const float* bqkv_i = bqkv + (size_t)i*3*EMBD;
        const bf16* woh = pwoh + (size_t)i*EMBD*EMBD;
        const bf16* wol = pwol + (size_t)i*EMBD*EMBD;
        const float* bo_i = bo + (size_t)i*EMBD;
        const float* wg_i = Wg + (size_t)i*EMBD*NEXP;
        const float* bg_i = bg + (size_t)i*NEXP;
        const bf16* w1h = pw1h + (size_t)i*NEXP*FFD*EMBD;
        const bf16* w1l = pw1l + (size_t)i*NEXP*FFD*EMBD;
        const float* b1_i = b1 + (size_t)i*NEXP*FFD;
        const bf16* w2h = pw2h + (size_t)i*EMBD*NEXP*FFD;
        const bf16* w2l = pw2l + (size_t)i*EMBD*NEXP*FFD;
        const float* b2_i = b2 + (size_t)i*NEXP*EMBD;

        if (i > 0) {
            ln_warp_p<<<NTOK/8, 256>>>(px, phh, phl, ln1_w + i*EMBD, ln1_b + i*EMBD, 0, 1);
            gemm_p<0><<<dim3(3, NTOK/64), 256, GEMM_SMEM>>>(phh, phl, EMBD, wqh, wql, bqkv_i,
                                                  pqkv, 3*EMBD, nullptr, nullptr,
                                                  nullptr, 0, EMBD);
        }

        int q0 = (i == NLAYER-1) ? 200 : 0;
        attn_mma<<<BATCH*NHEAD, 256, ATTN_SMEM>>>(pqkv, poh, pol, q0);

        if (i < NLAYER-1) {
            gemm_p<3><<<dim3(1, NTOK/64), 256, GEMM_SMEM>>>(poh, pol, EMBD, woh, wol, bo_i,
                                                  px, EMBD, nullptr, nullptr,
                                                  nullptr, 0, EMBD);
            ln2g_p<<<NTOK/8, 256>>>(px, phh, phl, ln2_w + i*EMBD, ln2_b + i*EMBD,
                                    wg_i, bg_i, pgate, 0, 1);
            gemm_p<1><<<dim3(10, NTOK/64), 256, GEMM_SMEM>>>(phh, phl, EMBD, w1h, w1l, b1_i,
                                                   nullptr, NEXP*FFD, phidh, phidl,
                                                   pgate, NEXP, EMBD);
            gemm_p<4><<<dim3(1, NTOK/64), 256, GEMM_SMEM>>>(phidh, phidl, NEXP*FFD, w2h, w2l, b2_i,
                                                  px, EMBD, nullptr, nullptr,
                                                  pgate, NEXP, NEXP*FFD);
        } else {
            const long rs = (long)SEQ*EMBD;
            gemm_p<3><<<dim3(1, BATCH/64), 256, GEMM_SMEM>>>(poh + (size_t)200*EMBD, pol + (size_t)200*EMBD, rs,
                                                   woh, wol, bo_i,
                                                   px + (size_t)200*EMBD, rs, nullptr, nullptr,
                                                   nullptr, 0, EMBD);
            ln2g_p<<<BATCH/8, 256>>>(px, phh, phl, ln2_w + i*EMBD, ln2_b + i*EMBD,
                                     wg_i, bg_i, pgate, 200, SEQ);
            gemm_p<1><<<dim3(10, BATCH/64), 256, GEMM_SMEM>>>(phh + (size_t)200*EMBD, phl + (size_t)200*EMBD, rs,
                                                    w1h, w1l, b1_i,
                                                    nullptr, NEXP*FFD, phidh, phidl,
                                                    pgate + (size_t)200*NEXP, (long)SEQ*NEXP, EMBD);
            gemm_p<4><<<dim3(1, BATCH/64), 256, GEMM_SMEM>>>(phidh, phidl, NEXP*FFD, w2h, w2l, b2_i,
                                                   px + (size_t)200*EMBD, rs, nullptr, nullptr,
                                                   pgate + (size_t)200*NEXP, (long)SEQ*NEXP,
                                                   NEXP*FFD);
        }
    }

    copy_out_kernel<<<BATCH, 128>>>(px, out);
}

// round 11
// speedup vs baseline: 1.0924x; 1.0924x over previous
#include <cuda_runtime.h>
#include <cuda_bf16.h>
#include <math.h>
#include <stdint.h>

#define BATCH 512
#define SEQ   201
#define EMBD  128
#define NHEAD 4
#define HDIM  32
#define FFD   256
#define NEXP  5
#define NLAYER 6
#define NTOK  (BATCH*SEQ)          // 102912

typedef __nv_bfloat16 bf16;

// ---------------- scratch (device globals; no runtime allocation) ----------
__device__ float g_x   [(size_t)NTOK*EMBD];
__device__ float g_qkv [(size_t)NTOK*3*EMBD];
__device__ float g_gate[(size_t)NTOK*NEXP];
__device__ bf16  g_hh  [(size_t)NTOK*EMBD];
__device__ bf16  g_hl  [(size_t)NTOK*EMBD];
__device__ bf16  g_oh  [(size_t)NTOK*EMBD];
__device__ bf16  g_ol  [(size_t)NTOK*EMBD];
__device__ bf16  g_hidh[(size_t)NTOK*NEXP*FFD];
__device__ bf16  g_hidl[(size_t)NTOK*NEXP*FFD];
// weight planes
__device__ bf16  g_wqkvh[(size_t)NLAYER*3*EMBD*EMBD], g_wqkvl[(size_t)NLAYER*3*EMBD*EMBD];
__device__ bf16  g_woh  [(size_t)NLAYER*EMBD*EMBD],   g_wol  [(size_t)NLAYER*EMBD*EMBD];
__device__ bf16  g_w1h  [(size_t)NLAYER*NEXP*FFD*EMBD], g_w1l[(size_t)NLAYER*NEXP*FFD*EMBD];
__device__ bf16  g_w2h  [(size_t)NLAYER*EMBD*NEXP*FFD], g_w2l[(size_t)NLAYER*EMBD*NEXP*FFD];

// ---------------- helpers -----------------------------------------------------
__device__ __forceinline__ void split2(float x, float y, uint32_t& hi, uint32_t& lo) {
    __nv_bfloat162 h, l;
    h.x = __float2bfloat16(x); h.y = __float2bfloat16(y);
    l.x = __float2bfloat16(x - __bfloat162float(h.x));
    l.y = __float2bfloat16(y - __bfloat162float(h.y));
    hi = *(uint32_t*)&h; lo = *(uint32_t*)&l;
}

#define MMA_BF16(d, a, b0, b1)                                                   \
    asm volatile("mma.sync.aligned.m16n8k16.row.col.f32.bf16.bf16.f32 "          \
                 "{%0,%1,%2,%3},{%4,%5,%6,%7},{%8,%9},{%0,%1,%2,%3};"            \
                 : "+f"(d[0]), "+f"(d[1]), "+f"(d[2]), "+f"(d[3])                 \
                 : "r"(a[0]), "r"(a[1]), "r"(a[2]), "r"(a[3]), "r"(b0), "r"(b1))

#define CP_ASYNC16(saddr, gaddr)                                                  \
    asm volatile("cp.async.cg.shared.global [%0], [%1], 16;" :: "r"(saddr), "l"(gaddr))

#define LDSM_X4(r0, r1, r2, r3, addr)                                             \
    asm volatile("ldmatrix.sync.aligned.m8n8.x4.shared.b16 {%0,%1,%2,%3}, [%4];"  \
                 : "=r"(r0), "=r"(r1), "=r"(r2), "=r"(r3) : "r"(addr))

#define LDSM_X2(r0, r1, addr)                                                     \
    asm volatile("ldmatrix.sync.aligned.m8n8.x2.shared.b16 {%0,%1}, [%2];"        \
                 : "=r"(r0), "=r"(r1) : "r"(addr))

// ---------------- fused embed+LN0 / weight-split prep -------------------------
// blocks [0, NTOK): embed + LN0 ; blocks [NTOK, NTOK+3072): Wqkv/Wo plane split
#define WSPLIT_N  (NLAYER*4*EMBD*EMBD)          // 393216 = 3072*128
#define PREP_GRID (NTOK + WSPLIT_N/128)

__global__ void prep_kernel(const int* __restrict__ x_cat,
                            const float* __restrict__ x_num,
                            const float* __restrict__ x_eng,
                            const float* __restrict__ emb,
                            const float* __restrict__ emb_bias,
                            const float* __restrict__ emb_eng,
                            const float* __restrict__ emb_bias_eng,
                            const float* __restrict__ w,
                            const float* __restrict__ bb,
                            float* __restrict__ xout,
                            const float* __restrict__ Wqkv,
                            bf16* __restrict__ wqh, bf16* __restrict__ wql,
                            const float* __restrict__ Wo,
                            bf16* __restrict__ woh, bf16* __restrict__ wol)
{
    if (blockIdx.x >= NTOK) {
        int i = (blockIdx.x - NTOK)*128 + threadIdx.x;
        const int na = NLAYER*3*EMBD*EMBD;
        if (i < na) {
            float v = Wqkv[i];
            bf16 h = __float2bfloat16(v);
            wqh[i] = h;
            wql[i] = __float2bfloat16(v - __bfloat162float(h));
        } else {
            int j = i - na;
            float v = Wo[j];
            bf16 h = __float2bfloat16(v);
            woh[j] = h;
            wol[j] = __float2bfloat16(v - __bfloat162float(h));
        }
        return;
    }

    int tok = blockIdx.x;
    int b = tok / SEQ, t = tok % SEQ;
    int j = threadIdx.x;

    float v;
    if (t < 53) {
        int idx = x_cat[(b*51 + 50)*53 + t];
        v = emb[(size_t)idx*EMBD + j] + emb_bias[t*EMBD + j];
    } else if (t < 100) {
        int c = t - 53;
        v = emb[(size_t)(1306 + c)*EMBD + j] * x_num[(b*51 + 50)*47 + c]
            + emb_bias[t*EMBD + j];
    } else if (t < 200) {
        int c = t - 100;
        v = emb_eng[c*EMBD + j] * x_eng[b*100 + c] + emb_bias_eng[c*EMBD + j];
    } else {
        v = 0.f;
    }

    __shared__ float red[8];
    int lane = j & 31, warp = j >> 5;
    float s = v;
    #pragma unroll
    for (int o = 16; o; o >>= 1) s += __shfl_xor_sync(0xffffffffu, s, o);
    if (lane == 0) red[warp] = s;
    __syncthreads();
    float m = (red[0] + red[1] + red[2] + red[3]) * (1.f/128.f);
    float d = v - m;
    float s2 = d * d;
    #pragma unroll
    for (int o = 16; o; o >>= 1) s2 += __shfl_xor_sync(0xffffffffu, s2, o);
    if (lane == 0) red[4 + warp] = s2;
    __syncthreads();
    float var = (red[4] + red[5] + red[6] + red[7]) * (1.f/128.f);
    xout[(size_t)tok*EMBD + j] = d * rsqrtf(var + 1e-5f) * w[j] + bb[j];
}

__global__ void trans_split(const float* __restrict__ in, bf16* __restrict__ oh,
                            bf16* __restrict__ ol, int R, int C)
{
    __shared__ float tile[32][33];
    int mat = blockIdx.z;
    const float* src = in + (size_t)mat*R*C;
    int c0 = blockIdx.x*32, r0 = blockIdx.y*32;
    int x = threadIdx.x, y = threadIdx.y;
    #pragma unroll
    for (int i = 0; i < 32; i += 8)
        tile[y+i][x] = src[(size_t)(r0+y+i)*C + c0+x];
    __syncthreads();
    #pragma unroll
    for (int i = 0; i < 32; i += 8) {
        float v = tile[x][y+i];
        size_t idx = (size_t)mat*R*C + (size_t)(c0+y+i)*R + r0+x;
        bf16 h = __float2bfloat16(v);
        oh[idx] = h;
        ol[idx] = __float2bfloat16(v - __bfloat162float(h));
    }
}

// ---------------- warp-per-token LayerNorm -> bf16 hi/lo planes ---------------
__global__ void ln_warp_p(const float* __restrict__ src,
                          bf16* __restrict__ dh, bf16* __restrict__ dl,
                          const float* __restrict__ w, const float* __restrict__ bb,
                          int t0, int tstride)
{
    int lane = threadIdx.x & 31;
    int tokl = blockIdx.x * (blockDim.x >> 5) + (threadIdx.x >> 5);
    size_t tok = (size_t)t0 + (size_t)tokl * tstride;

    float4 v = *(const float4*)(src + tok*EMBD + lane*4);
    float s = v.x + v.y + v.z + v.w;
    #pragma unroll
    for (int o = 16; o; o >>= 1) s += __shfl_xor_sync(0xffffffffu, s, o);
    float m = s * (1.f/128.f);
    float dx = v.x-m, dy = v.y-m, dz = v.z-m, dw = v.w-m;
    float s2 = dx*dx + dy*dy + dz*dz + dw*dw;
    #pragma unroll
    for (int o = 16; o; o >>= 1) s2 += __shfl_xor_sync(0xffffffffu, s2, o);
    float inv = rsqrtf(s2 * (1.f/128.f) + 1e-5f);
    float4 wv = *(const float4*)(w + lane*4);
    float4 bv = *(const float4*)(bb + lane*4);
    float r0 = dx*inv*wv.x + bv.x, r1 = dy*inv*wv.y + bv.y;
    float r2 = dz*inv*wv.z + bv.z, r3 = dw*inv*wv.w + bv.w;
    uint32_t h0,l0,h1,l1;
    split2(r0, r1, h0, l0); split2(r2, r3, h1, l1);
    uint32_t* ph = (uint32_t*)(dh + tok*EMBD + lane*4);
    uint32_t* pl = (uint32_t*)(dl + tok*EMBD + lane*4);
    ph[0] = h0; ph[1] = h1; pl[0] = l0; pl[1] = l1;
}

// ---------------- fused LN2 + gate softmax -> planes --------------------------
__global__ void ln2g_p(const float* __restrict__ src,
                       bf16* __restrict__ dh, bf16* __restrict__ dl,
                       const float* __restrict__ w, const float* __restrict__ bb,
                       const float* __restrict__ Wg, const float* __restrict__ bg,
                       float* __restrict__ gate, int t0, int tstride)
{
    int lane = threadIdx.x & 31;
    int tokl = blockIdx.x * (blockDim.x >> 5) + (threadIdx.x >> 5);
    size_t tok = (size_t)t0 + (size_t)tokl * tstride;

    float4 v = *(const float4*)(src + tok*EMBD + lane*4);
    float s = v.x + v.y + v.z + v.w;
    #pragma unroll
    for (int o = 16; o; o >>= 1) s += __shfl_xor_sync(0xffffffffu, s, o);
    float m = s * (1.f/128.f);
    float dx = v.x-m, dy = v.y-m, dz = v.z-m, dw = v.w-m;
    float s2 = dx*dx + dy*dy + dz*dz + dw*dw;
    #pragma unroll
    for (int o = 16; o; o >>= 1) s2 += __shfl_xor_sync(0xffffffffu, s2, o);
    float inv = rsqrtf(s2 * (1.f/128.f) + 1e-5f);
    float4 wv = *(const float4*)(w + lane*4);
    float4 bv = *(const float4*)(bb + lane*4);
    float h[4];
    h[0] = dx*inv*wv.x + bv.x; h[1] = dy*inv*wv.y + bv.y;
    h[2] = dz*inv*wv.z + bv.z; h[3] = dw*inv*wv.w + bv.w;
    uint32_t hh0,ll0,hh1,ll1;
    split2(h[0], h[1], hh0, ll0); split2(h[2], h[3], hh1, ll1);
    uint32_t* ph = (uint32_t*)(dh + tok*EMBD + lane*4);
    uint32_t* pl = (uint32_t*)(dl + tok*EMBD + lane*4);
    ph[0] = hh0; ph[1] = hh1; pl[0] = ll0; pl[1] = ll1;

    float p[NEXP];
    #pragma unroll
    for (int e = 0; e < NEXP; e++) p[e] = 0.f;
    #pragma unroll
    for (int q = 0; q < 4; q++) {
        int j = lane*4 + q;
        #pragma unroll
        for (int e = 0; e < NEXP; e++) p[e] += h[q] * Wg[j*NEXP + e];
    }
    #pragma unroll
    for (int e = 0; e < NEXP; e++)
        #pragma unroll
        for (int o = 16; o; o >>= 1) p[e] += __shfl_xor_sync(0xffffffffu, p[e], o);
    if (lane == 0) {
        float mx = -1e30f;
        #pragma unroll
        for (int e = 0; e < NEXP; e++) { p[e] += bg[e]; mx = fmaxf(mx, p[e]); }
        float sum = 0.f;
        #pragma unroll
        for (int e = 0; e < NEXP; e++) { p[e] = __expf(p[e] - mx); sum += p[e]; }
        float is = 1.f / sum;
        #pragma unroll
        for (int e = 0; e < NEXP; e++) gate[tok*NEXP + e] = p[e] * is;
    }
}

// ---------------- bf16x3 GEMM: ldmatrix + 3-stage cp.async (R9 config) --------
// C[M,N] = A @ B^T ; 256 threads, CTA tile 128x128, 8 warps of 32x64, 2 CTAs/SM.
// EPI 0: C = acc+bias ; EPI 1: planes = split(relu(acc+bias)*gate[m][bx>>1])
// EPI 3: C += acc+bias ; EPI 4: C += acc + sum_e gate[m][e]*bias[e*128+n]
#define GEMM_KP   24
#define GEMM_PL   (128*GEMM_KP)
#define GEMM_SMEM (4*3*GEMM_PL*2)   // 73728 bytes

template<int EPI>
__global__ void __launch_bounds__(256, 2)
gemm_p(const bf16* __restrict__ Ahp, const bf16* __restrict__ Alp, long rsA,
       const bf16* __restrict__ Bhp, const bf16* __restrict__ Blp,
       const float* __restrict__ bias,
       float* __restrict__ C, long rsC,
       bf16* __restrict__ Chp, bf16* __restrict__ Clp,
       const float* __restrict__ gate, long rsG,
       int K)
{
    constexpr int KP = GEMM_KP;
    constexpr int PL = GEMM_PL;
    extern __shared__ bf16 smg[];
    bf16* Ah = smg;
    bf16* Al = Ah + 3*PL;
    bf16* Bh = Al + 3*PL;
    bf16* Bl = Bh + 3*PL;

    const int tid  = threadIdx.x;
    const int warp = tid >> 5, lane = tid & 31;
    const int g = lane >> 2, r = lane & 3;
    const int wm = (warp & 3) * 32;
    const int wn = (warp >> 2) * 64;
    const int bx = blockIdx.x, by = blockIdx.y;

    float c[2][8][4];
    #pragma unroll
    for (int mi = 0; mi < 2; mi++)
        #pragma unroll
        for (int ni = 0; ni < 8; ni++)
            #pragma unroll
            for (int q = 0; q < 4; q++) c[mi][ni][q] = 0.f;

    const int crow = tid >> 1;
    const int ckseg = (tid & 1) << 3;
    const bf16* gAh = Ahp + (size_t)(by*128 + crow)*rsA + ckseg;
    const bf16* gAl = Alp + (size_t)(by*128 + crow)*rsA + ckseg;
    const bf16* gBh = Bhp + (size_t)(bx*128 + crow)*K + ckseg;
    const bf16* gBl = Blp + (size_t)(bx*128 + crow)*K + ckseg;

    uint32_t baseAh = (uint32_t)__cvta_generic_to_shared(Ah);
    uint32_t baseAl = (uint32_t)__cvta_generic_to_shared(Al);
    uint32_t baseBh = (uint32_t)__cvta_generic_to_shared(Bh);
    uint32_t baseBl = (uint32_t)__cvta_generic_to_shared(Bl);

    auto stage = [&](int k0, int s) {
        uint32_t off = (uint32_t)(s*PL + crow*KP + ckseg) * 2;
        CP_ASYNC16(baseAh + off, gAh + k0);
        CP_ASYNC16(baseAl + off, gAl + k0);
        CP_ASYNC16(baseBh + off, gBh + k0);
        CP_ASYNC16(baseBl + off, gBl + k0);
        asm volatile("cp.async.commit_group;" ::: "memory");
    };

    uint32_t a_off[2];
    #pragma unroll
    for (int mi = 0; mi < 2; mi++)
        a_off[mi] = (uint32_t)(((wm + mi*16 + (lane & 15))*KP + ((lane >> 4) << 3)) * 2);
    uint32_t b_off[4];
    #pragma unroll
    for (int p = 0; p < 4; p++)
        b_off[p] = (uint32_t)(((wn + p*16 + (lane & 7) + ((lane >> 4) << 3))*KP
                               + (((lane >> 3) & 1) << 3)) * 2);

    auto compute = [&](int s) {
        uint32_t so = (uint32_t)(s*PL*2);
        uint32_t ah[2][4], al[2][4];
        #pragma unroll
        for (int mi = 0; mi < 2; mi++) {
            LDSM_X4(ah[mi][0], ah[mi][1], ah[mi][2], ah[mi][3], baseAh + so + a_off[mi]);
            LDSM_X4(al[mi][0], al[mi][1], al[mi][2], al[mi][3], baseAl + so + a_off[mi]);
        }
        #pragma unroll
        for (int p = 0; p < 4; p++) {
            uint32_t bh[4], bl[4];
            LDSM_X4(bh[0], bh[1], bh[2], bh[3], baseBh + so + b_off[p]);
            LDSM_X4(bl[0], bl[1], bl[2], bl[3], baseBl + so + b_off[p]);
            MMA_BF16(c[0][2*p],   ah[0], bh[0], bh[1]);
            MMA_BF16(c[1][2*p],   ah[1], bh[0], bh[1]);
            MMA_BF16(c[0][2*p+1], ah[0], bh[2], bh[3]);
            MMA_BF16(c[1][2*p+1], ah[1], bh[2], bh[3]);
            MMA_BF16(c[0][2*p],   al[0], bh[0], bh[1]);
            MMA_BF16(c[1][2*p],   al[1], bh[0], bh[1]);
            MMA_BF16(c[0][2*p+1], al[0], bh[2], bh[3]);
            MMA_BF16(c[1][2*p+1], al[1], bh[2], bh[3]);
            MMA_BF16(c[0][2*p],   ah[0], bl[0], bl[1]);
            MMA_BF16(c[1][2*p],   ah[1], bl[0], bl[1]);
            MMA_BF16(c[0][2*p+1], ah[0], bl[2], bl[3]);
            MMA_BF16(c[1][2*p+1], ah[1], bl[2], bl[3]);
        }
    };

    const int nk = K >> 4;
    stage(0, 0);
    if (nk > 1) stage(16, 1);
    for (int it = 0; it < nk; ++it) {
        if (it + 1 < nk) asm volatile("cp.async.wait_group 1;" ::: "memory");
        else             asm volatile("cp.async.wait_group 0;" ::: "memory");
        __syncthreads();
        compute(it % 3);
        if (it + 2 < nk) stage((it + 2) << 4, (it + 2) % 3);
    }

    // ---------------- epilogue ----------------
    if (EPI == 4) {
        #pragma unroll
        for (int mi = 0; mi < 2; mi++)
            #pragma unroll
            for (int half = 0; half < 2; half++) {
                int m = by*128 + wm + mi*16 + g + half*8;
                float gg[NEXP];
                #pragma unroll
                for (int e = 0; e < NEXP; e++) gg[e] = gate[(size_t)m*rsG + e];
                float* crow2 = C + (size_t)m*rsC;
                #pragma unroll
                for (int ni = 0; ni < 8; ni++) {
                    int col = wn + ni*8 + 2*r;
                    float a0 = 0.f, a1 = 0.f;
                    #pragma unroll
                    for (int e = 0; e < NEXP; e++) {
                        a0 += gg[e] * bias[e*128 + col];
                        a1 += gg[e] * bias[e*128 + col + 1];
                    }
                    float2 old = *(float2*)(crow2 + col);
                    old.x += c[mi][ni][half*2 + 0] + a0;
                    old.y += c[mi][ni][half*2 + 1] + a1;
                    *(float2*)(crow2 + col) = old;
                }
            }
    } else if (EPI == 1) {
        #pragma unroll
        for (int mi = 0; mi < 2; mi++)
            #pragma unroll
            for (int half = 0; half < 2; half++) {
                int m = by*128 + wm + mi*16 + g + half*8;
                float gv = gate[(size_t)m*rsG + (bx >> 1)];
                #pragma unroll
                for (int ni = 0; ni < 8; ni++) {
                    int n = wn + ni*8 + 2*r;
                    float v0 = fmaxf(c[mi][ni][half*2+0] + bias[bx*128 + n],   0.f) * gv;
                    float v1 = fmaxf(c[mi][ni][half*2+1] + bias[bx*128 + n+1], 0.f) * gv;
                    uint32_t hi, lo;
                    split2(v0, v1, hi, lo);
                    *(uint32_t*)(Chp + (size_t)m*rsC + bx*128 + n) = hi;
                    *(uint32_t*)(Clp + (size_t)m*rsC + bx*128 + n) = lo;
                }
            }
    } else {
        #pragma unroll
        for (int mi = 0; mi < 2; mi++)
            #pragma unroll
            for (int half = 0; half < 2; half++) {
                int m = by*128 + wm + mi*16 + g + half*8;
                float* crow2 = C + (size_t)m*rsC + bx*128;
                const float* brow = bias + bx*128;
                #pragma unroll
                for (int ni = 0; ni < 8; ni++) {
                    int n = wn + ni*8 + 2*r;
                    float v0 = c[mi][ni][half*2 + 0] + brow[n];
                    float v1 = c[mi][ni][half*2 + 1] + brow[n+1];
                    if (EPI == 0) {
                        *(float2*)(crow2 + n) = make_float2(v0, v1);
                    } else {
                        float2 old = *(float2*)(crow2 + n);
                        old.x += v0; old.y += v1;
                        *(float2*)(crow2 + n) = old;
                    }
                }
            }
    }
}

// ---------------- mma attention (no max-shift softmax) -------------------------
#define KSTR 40
#define VSTR 216
#define PSTR 232
#define ATTN_SMEM (208*KSTR*2*2 + 32*VSTR*2*2 + 32*PSTR*2*2 + 8*32*4)  // 91648

__global__ void __launch_bounds__(256, 2)
attn_mma(const float* __restrict__ qkv, bf16* __restrict__ ohi, bf16* __restrict__ olo,
         int q0)
{
    extern __shared__ char smraw[];
    bf16* Kh = (bf16*)smraw;                 // [208][KSTR]
    bf16* Kl = Kh + 208*KSTR;
    bf16* Vh = Kl + 208*KSTR;                // [32][VSTR]  (V transposed: [d][key])
    bf16* Vl = Vh + 32*VSTR;
    bf16* Ph = Vl + 32*VSTR;                 // [32][PSTR]
    bf16* Pl = Ph + 32*PSTR;
    float* wsum = (float*)(Pl + 32*PSTR);    // [32 rows][8 warps]

    const int bh0_ = blockIdx.x, b = bh0_ >> 2, h = bh0_ & 3;
    const float* base = qkv + (size_t)b*SEQ*(3*EMBD) + h*HDIM;
    const int tid = threadIdx.x, warp = tid >> 5, lane = tid & 31;
    const int g = lane >> 2, r = lane & 3;
    const float scale = 0.1767766952966369f;   // 1/sqrt(32)

    uint32_t baseKh = (uint32_t)__cvta_generic_to_shared(Kh);
    uint32_t baseKl = (uint32_t)__cvta_generic_to_shared(Kl);
    uint32_t baseVh = (uint32_t)__cvta_generic_to_shared(Vh);
    uint32_t baseVl = (uint32_t)__cvta_generic_to_shared(Vl);
    uint32_t basePh = (uint32_t)__cvta_generic_to_shared(Ph);
    uint32_t basePl = (uint32_t)__cvta_generic_to_shared(Pl);

    for (int idx = tid; idx < 208*32; idx += 256) {
        int t = idx >> 5, d = idx & 31;
        float kv = 0.f, vv = 0.f;
        if (t < SEQ) {
            kv = base[(size_t)t*(3*EMBD) + EMBD   + d];
            vv = base[(size_t)t*(3*EMBD) + 2*EMBD + d];
        }
        bf16 khv = __float2bfloat16(kv);
        Kh[t*KSTR + d] = khv;
        Kl[t*KSTR + d] = __float2bfloat16(kv - __bfloat162float(khv));
        bf16 vhv = __float2bfloat16(vv);
        Vh[d*VSTR + t] = vhv;
        Vl[d*VSTR + t] = __float2bfloat16(vv - __bfloat162float(vhv));
    }
    __syncthreads();

    const uint32_t kofl = (uint32_t)((((lane & 7))*KSTR + (((lane >> 3) & 3) << 3)) * 2);
    const uint32_t pofl = (uint32_t)(((lane & 15))*PSTR*2 + (((lane >> 4) << 3)) * 2);
    const uint32_t vofl = (uint32_t)((((lane & 7))*VSTR + (((lane >> 3) & 1) << 3)) * 2);

    for (int qt = q0; qt < SEQ; qt += 32) {
        uint32_t qh[2][2][4], ql[2][2][4];
        #pragma unroll
        for (int mi = 0; mi < 2; mi++)
            #pragma unroll
            for (int ks = 0; ks < 2; ks++)
                #pragma unroll
                for (int j = 0; j < 4; j++) {
                    int qq = qt + mi*16 + g + (j & 1)*8;
                    if (qq > 200) qq = 200;
                    int kk = ks*16 + 2*r + (j >> 1)*8;
                    float2 v = *(const float2*)(base + (size_t)qq*(3*EMBD) + kk);
                    split2(v.x*scale, v.y*scale, qh[mi][ks][j], ql[mi][ks][j]);
                }

        float sc[4][2][4];
        #pragma unroll
        for (int ti = 0; ti < 4; ti++)
            #pragma unroll
            for (int mi = 0; mi < 2; mi++)
                #pragma unroll
                for (int q = 0; q < 4; q++) sc[ti][mi][q] = 0.f;

        #pragma unroll
        for (int ti = 0; ti < 4; ti++) {
            int t = warp + ti*8;
            if (t < 26) {
                uint32_t ko = (uint32_t)(t*8*KSTR*2) + kofl;
                uint32_t bhv[4], blv[4];
                LDSM_X4(bhv[0], bhv[1], bhv[2], bhv[3], baseKh + ko);
                LDSM_X4(blv[0], blv[1], blv[2], blv[3], baseKl + ko);
                MMA_BF16(sc[ti][0], qh[0][0], bhv[0], bhv[1]);
                MMA_BF16(sc[ti][1], qh[1][0], bhv[0], bhv[1]);
                MMA_BF16(sc[ti][0], ql[0][0], bhv[0], bhv[1]);
                MMA_BF16(sc[ti][1], ql[1][0], bhv[0], bhv[1]);
                MMA_BF16(sc[ti][0], qh[0][0], blv[0], blv[1]);
                MMA_BF16(sc[ti][1], qh[1][0], blv[0], blv[1]);
                MMA_BF16(sc[ti][0], qh[0][1], bhv[2], bhv[3]);
                MMA_BF16(sc[ti][1], qh[1][1], bhv[2], bhv[3]);
                MMA_BF16(sc[ti][0], ql[0][1], bhv[2], bhv[3]);
                MMA_BF16(sc[ti][1], ql[1][1], bhv[2], bhv[3]);
                MMA_BF16(sc[ti][0], qh[0][1], blv[2], blv[3]);
                MMA_BF16(sc[ti][1], qh[1][1], blv[2], blv[3]);
            }
        }

        // ---- softmax without max-shift (scores are small; fp32 exp is exact
        //      to rounding and matches the reference mathematically)
        float gs[2][2];
        #pragma unroll
        for (int mi = 0; mi < 2; mi++)
            #pragma unroll
            for (int h2 = 0; h2 < 2; h2++) {
                float s = 0.f;
                #pragma unroll
                for (int ti = 0; ti < 4; ti++) {
                    int t = warp + ti*8;
                    if (t < 26) {
                        int c0 = t*8 + 2*r;
                        float p0 = (c0     <= 200) ? __expf(sc[ti][mi][h2*2+0]) : 0.f;
                        float p1 = (c0 + 1 <= 200) ? __expf(sc[ti][mi][h2*2+1]) : 0.f;
                        sc[ti][mi][h2*2+0] = p0; sc[ti][mi][h2*2+1] = p1;
                        s += p0 + p1;
                    }
                }
                s += __shfl_xor_sync(0xffffffffu, s, 1);
                s += __shfl_xor_sync(0xffffffffu, s, 2);
                if (r == 0) wsum[(mi*16 + g + h2*8)*8 + warp] = s;
            }
        __syncthreads();
        #pragma unroll
        for (int mi = 0; mi < 2; mi++)
            #pragma unroll
            for (int h2 = 0; h2 < 2; h2++) {
                int row = mi*16 + g + h2*8;
                float s = 0.f;
                #pragma unroll
                for (int w2 = 0; w2 < 8; w2++) s += wsum[row*8 + w2];
                gs[mi][h2] = 1.f / s;
            }
        #pragma unroll
        for (int ti = 0; ti < 4; ti++) {
            int t = warp + ti*8;
            if (t < 26) {
                int c0 = t*8 + 2*r;
                #pragma unroll
                for (int mi = 0; mi < 2; mi++)
                    #pragma unroll
                    for (int h2 = 0; h2 < 2; h2++) {
                        int row = mi*16 + g + h2*8;
                        uint32_t hi, lo;
                        split2(sc[ti][mi][h2*2+0]*gs[mi][h2],
                               sc[ti][mi][h2*2+1]*gs[mi][h2], hi, lo);
                        *(uint32_t*)(Ph + row*PSTR + c0) = hi;
                        *(uint32_t*)(Pl + row*PSTR + c0) = lo;
                    }
            }
        }
        __syncthreads();

        {
            int mi = warp >> 2, ni = warp & 3;
            float oc[4] = {0.f, 0.f, 0.f, 0.f};
            #pragma unroll
            for (int ks = 0; ks < 13; ks++) {
                uint32_t po = (uint32_t)((mi*16*PSTR + ks*16) * 2) + pofl;
                uint32_t ah[4], al[4];
                LDSM_X4(ah[0], ah[1], ah[2], ah[3], basePh + po);
                LDSM_X4(al[0], al[1], al[2], al[3], basePl + po);
                uint32_t vo = (uint32_t)((ni*8*VSTR + ks*16) * 2) + vofl;
                uint32_t bh0, bh1, bl0, bl1;
                LDSM_X2(bh0, bh1, baseVh + vo);
                LDSM_X2(bl0, bl1, baseVl + vo);
                MMA_BF16(oc, ah, bh0, bh1);
                MMA_BF16(oc, al, bh0, bh1);
                MMA_BF16(oc, ah, bl0, bl1);
            }
            #pragma unroll
            for (int h2 = 0; h2 < 2; h2++) {
                int q = qt + mi*16 + g + h2*8;
                if (q <= 200) {
                    int d = ni*8 + 2*r;
                    uint32_t hi, lo;
                    split2(oc[h2*2+0], oc[h2*2+1], hi, lo);
                    size_t off = ((size_t)b*SEQ + q)*EMBD + h*HDIM + d;
                    *(uint32_t*)(ohi + off) = hi;
                    *(uint32_t*)(olo + off) = lo;
                }
            }
        }
        __syncthreads();
    }
}

// ---------------- output copy -------------------------------------------------
__global__ void copy_out_kernel(const float* __restrict__ x, float* __restrict__ out)
{
    int b = blockIdx.x, j = threadIdx.x;
    out[b*EMBD + j] = x[((size_t)b*SEQ + 200)*EMBD + j];
}

// ---------------- launcher ----------------------------------------------------
extern "C" void kernel_launch(void* const* d_in, const int* in_sizes, int n_in,
                              void* d_out, int out_size)
{
    (void)in_sizes; (void)n_in; (void)out_size;

    const int*   x_cat        = (const int*)  d_in[0];
    const float* x_num        = (const float*)d_in[1];
    const float* x_eng        = (const float*)d_in[2];
    const float* emb          = (const float*)d_in[3];
    const float* emb_bias     = (const float*)d_in[4];
    const float* emb_eng      = (const float*)d_in[5];
    const float* emb_bias_eng = (const float*)d_in[6];
    const float* ln0_w        = (const float*)d_in[7];
    const float* ln0_b        = (const float*)d_in[8];
    const float* ln1_w        = (const float*)d_in[9];
    const float* ln1_b        = (const float*)d_in[10];
    const float* Wqkv         = (const float*)d_in[11];
    const float* bqkv         = (const float*)d_in[12];
    const float* Wo           = (const float*)d_in[13];
    const float* bo           = (const float*)d_in[14];
    const float* ln2_w        = (const float*)d_in[15];
    const float* ln2_b        = (const float*)d_in[16];
    const float* Wg           = (const float*)d_in[17];
    const float* bg           = (const float*)d_in[18];
    const float* W1           = (const float*)d_in[19];
    const float* b1           = (const float*)d_in[20];
    const float* W2           = (const float*)d_in[21];
    const float* b2           = (const float*)d_in[22];
    float* out = (float*)d_out;

    float *px, *pqkv, *pgate;
    bf16 *phh, *phl, *poh, *pol, *phidh, *phidl;
    bf16 *pwqkvh, *pwqkvl, *pwoh, *pwol, *pw1h, *pw1l, *pw2h, *pw2l;
    cudaGetSymbolAddress((void**)&px,    g_x);
    cudaGetSymbolAddress((void**)&pqkv,  g_qkv);
    cudaGetSymbolAddress((void**)&pgate, g_gate);
    cudaGetSymbolAddress((void**)&phh,   g_hh);
    cudaGetSymbolAddress((void**)&phl,   g_hl);
    cudaGetSymbolAddress((void**)&poh,   g_oh);
    cudaGetSymbolAddress((void**)&pol,   g_ol);
    cudaGetSymbolAddress((void**)&phidh, g_hidh);
    cudaGetSymbolAddress((void**)&phidl, g_hidl);
    cudaGetSymbolAddress((void**)&pwqkvh, g_wqkvh);
    cudaGetSymbolAddress((void**)&pwqkvl, g_wqkvl);
    cudaGetSymbolAddress((void**)&pwoh,   g_woh);
    cudaGetSymbolAddress((void**)&pwol,   g_wol);
    cudaGetSymbolAddress((void**)&pw1h,   g_w1h);
    cudaGetSymbolAddress((void**)&pw1l,   g_w1l);
    cudaGetSymbolAddress((void**)&pw2h,   g_w2h);
    cudaGetSymbolAddress((void**)&pw2l,   g_w2l);

    cudaFuncSetAttribute(attn_mma, cudaFuncAttributeMaxDynamicSharedMemorySize, ATTN_SMEM);
    cudaFuncSetAttribute(gemm_p<0>, cudaFuncAttributeMaxDynamicSharedMemorySize, GEMM_SMEM);
    cudaFuncSetAttribute(gemm_p<1>, cudaFuncAttributeMaxDynamicSharedMemorySize, GEMM_SMEM);
    cudaFuncSetAttribute(gemm_p<3>, cudaFuncAttributeMaxDynamicSharedMemorySize, GEMM_SMEM);
    cudaFuncSetAttribute(gemm_p<4>, cudaFuncAttributeMaxDynamicSharedMemorySize, GEMM_SMEM);

    // launch order: #4 (ncu capture slot) = layer-0 attention
    prep_kernel<<<PREP_GRID, 128>>>(x_cat, x_num, x_eng, emb, emb_bias,
                                    emb_eng, emb_bias_eng, ln0_w, ln0_b, px,
                                    Wqkv, pwqkvh, pwqkvl, Wo, pwoh, pwol);       // 1
    ln_warp_p<<<NTOK/8, 256>>>(px, phh, phl, ln1_w, ln1_b, 0, 1);                // 2
    gemm_p<0><<<dim3(3, NTOK/128), 256, GEMM_SMEM>>>(phh, phl, EMBD,
                                              pwqkvh, pwqkvl, bqkv,
                                              pqkv, 3*EMBD, nullptr, nullptr,
                                              nullptr, 0, EMBD);                 // 3
    attn_mma<<<BATCH*NHEAD, 256, ATTN_SMEM>>>(pqkv, poh, pol, 0);                // 4 (profiled)
    trans_split<<<dim3(FFD/32, EMBD/32, NLAYER*NEXP), dim3(32,8)>>>(W1, pw1h, pw1l, EMBD, FFD);
    trans_split<<<dim3(EMBD/32, (NEXP*FFD)/32, NLAYER), dim3(32,8)>>>(W2, pw2h, pw2l, NEXP*FFD, EMBD);

    for (int i = 0; i < NLAYER; i++) {
        const bf16* wqh = pwqkvh + (size_t)i*3*EMBD*EMBD;
        const bf16* wql = pwqkvl + (size_t)i*3*EMBD*EMBD;
        const float* bqkv_i = bqkv + (size_t)i*3*EMBD;
        const bf16* woh = pwoh + (size_t)i*EMBD*EMBD;
        const bf16* wol = pwol + (size_t)i*EMBD*EMBD;
        const float* bo_i = bo + (size_t)i*EMBD;
        const float* wg_i = Wg + (size_t)i*EMBD*NEXP;
        const float* bg_i = bg + (size_t)i*NEXP;
        const bf16* w1h = pw1h + (size_t)i*NEXP*FFD*EMBD;
        const bf16* w1l = pw1l + (size_t)i*NEXP*FFD*EMBD;
        const float* b1_i = b1 + (size_t)i*NEXP*FFD;
        const bf16* w2h = pw2h + (size_t)i*EMBD*NEXP*FFD;
        const bf16* w2l = pw2l + (size_t)i*EMBD*NEXP*FFD;
        const float* b2_i = b2 + (size_t)i*NEXP*EMBD;

        if (i > 0) {
            ln_warp_p<<<NTOK/8, 256>>>(px, phh, phl, ln1_w + i*EMBD, ln1_b + i*EMBD, 0, 1);
            gemm_p<0><<<dim3(3, NTOK/128), 256, GEMM_SMEM>>>(phh, phl, EMBD, wqh, wql, bqkv_i,
                                                  pqkv, 3*EMBD, nullptr, nullptr,
                                                  nullptr, 0, EMBD);
            int q0 = (i == NLAYER-1) ? 200 : 0;
            attn_mma<<<BATCH*NHEAD, 256, ATTN_SMEM>>>(pqkv, poh, pol, q0);
        }

        if (i < NLAYER-1) {
            gemm_p<3><<<dim3(1, NTOK/128), 256, GEMM_SMEM>>>(poh, pol, EMBD, woh, wol, bo_i,
                                                  px, EMBD, nullptr, nullptr,
                                                  nullptr, 0, EMBD);
            ln2g_p<<<NTOK/8, 256>>>(px, phh, phl, ln2_w + i*EMBD, ln2_b + i*EMBD,
                                    wg_i, bg_i, pgate, 0, 1);
            gemm_p<1><<<dim3(10, NTOK/128), 256, GEMM_SMEM>>>(phh, phl, EMBD, w1h, w1l, b1_i,
                                                   nullptr, NEXP*FFD, phidh, phidl,
                                                   pgate, NEXP, EMBD);
            gemm_p<4><<<dim3(1, NTOK/128), 256, GEMM_SMEM>>>(phidh, phidl, NEXP*FFD, w2h, w2l, b2_i,
                                                  px, EMBD, nullptr, nullptr,
                                                  pgate, NEXP, NEXP*FFD);
        } else {
            const long rs = (long)SEQ*EMBD;
            gemm_p<3><<<dim3(1, BATCH/128), 256, GEMM_SMEM>>>(poh + (size_t)200*EMBD, pol + (size_t)200*EMBD, rs,
                                                   woh, wol, bo_i,
                                                   px + (size_t)200*EMBD, rs, nullptr, nullptr,
                                                   nullptr, 0, EMBD);
            ln2g_p<<<BATCH/8, 256>>>(px, phh, phl, ln2_w + i*EMBD, ln2_b + i*EMBD,
                                     wg_i, bg_i, pgate, 200, SEQ);
            gemm_p<1><<<dim3(10, BATCH/128), 256, GEMM_SMEM>>>(phh + (size_t)200*EMBD, phl + (size_t)200*EMBD, rs,
                                                    w1h, w1l, b1_i,
                                                    nullptr, NEXP*FFD, phidh, phidl,
                                                    pgate + (size_t)200*NEXP, (long)SEQ*NEXP, EMBD);
            gemm_p<4><<<dim3(1, BATCH/128), 256, GEMM_SMEM>>>(phidh, phidl, NEXP*FFD, w2h, w2l, b2_i,
                                                   px + (size_t)200*EMBD, rs, nullptr, nullptr,
                                                   pgate + (size_t)200*NEXP, (long)SEQ*NEXP,
                                                   NEXP*FFD);
        }
    }

    copy_out_kernel<<<BATCH, 128>>>(px, out);
}

// round 12
// speedup vs baseline: 1.2022x; 1.1004x over previous
#include <cuda_runtime.h>
#include <cuda_bf16.h>
#include <math.h>
#include <stdint.h>

#define BATCH 512
#define SEQ   201
#define EMBD  128
#define NHEAD 4
#define HDIM  32
#define FFD   256
#define NEXP  5
#define NLAYER 6
#define NTOK  (BATCH*SEQ)          // 102912

typedef __nv_bfloat16 bf16;

// ---------------- scratch (device globals; no runtime allocation) ----------
__device__ float g_x   [(size_t)NTOK*EMBD];
__device__ float g_qkv [(size_t)NTOK*3*EMBD];
__device__ float g_gate[(size_t)NTOK*NEXP];
__device__ bf16  g_hh  [(size_t)NTOK*EMBD];
__device__ bf16  g_hl  [(size_t)NTOK*EMBD];
__device__ bf16  g_oh  [(size_t)NTOK*EMBD];
__device__ bf16  g_ol  [(size_t)NTOK*EMBD];
__device__ bf16  g_hidh[(size_t)NTOK*NEXP*FFD];
__device__ bf16  g_hidl[(size_t)NTOK*NEXP*FFD];
// weight planes
__device__ bf16  g_wqkvh[(size_t)NLAYER*3*EMBD*EMBD], g_wqkvl[(size_t)NLAYER*3*EMBD*EMBD];
__device__ bf16  g_woh  [(size_t)NLAYER*EMBD*EMBD],   g_wol  [(size_t)NLAYER*EMBD*EMBD];
__device__ bf16  g_w1h  [(size_t)NLAYER*NEXP*FFD*EMBD], g_w1l[(size_t)NLAYER*NEXP*FFD*EMBD];
__device__ bf16  g_w2h  [(size_t)NLAYER*EMBD*NEXP*FFD], g_w2l[(size_t)NLAYER*EMBD*NEXP*FFD];

// ---------------- helpers -----------------------------------------------------
__device__ __forceinline__ void split2(float x, float y, uint32_t& hi, uint32_t& lo) {
    __nv_bfloat162 h, l;
    h.x = __float2bfloat16(x); h.y = __float2bfloat16(y);
    l.x = __float2bfloat16(x - __bfloat162float(h.x));
    l.y = __float2bfloat16(y - __bfloat162float(h.y));
    hi = *(uint32_t*)&h; lo = *(uint32_t*)&l;
}

#define MMA_BF16(d, a, b0, b1)                                                   \
    asm volatile("mma.sync.aligned.m16n8k16.row.col.f32.bf16.bf16.f32 "          \
                 "{%0,%1,%2,%3},{%4,%5,%6,%7},{%8,%9},{%0,%1,%2,%3};"            \
                 : "+f"(d[0]), "+f"(d[1]), "+f"(d[2]), "+f"(d[3])                 \
                 : "r"(a[0]), "r"(a[1]), "r"(a[2]), "r"(a[3]), "r"(b0), "r"(b1))

#define CP_ASYNC16(saddr, gaddr)                                                  \
    asm volatile("cp.async.cg.shared.global [%0], [%1], 16;" :: "r"(saddr), "l"(gaddr))

#define LDSM_X4(r0, r1, r2, r3, addr)                                             \
    asm volatile("ldmatrix.sync.aligned.m8n8.x4.shared.b16 {%0,%1,%2,%3}, [%4];"  \
                 : "=r"(r0), "=r"(r1), "=r"(r2), "=r"(r3) : "r"(addr))

#define LDSM_X2(r0, r1, addr)                                                     \
    asm volatile("ldmatrix.sync.aligned.m8n8.x2.shared.b16 {%0,%1}, [%2];"        \
                 : "=r"(r0), "=r"(r1) : "r"(addr))

// ---------------- fused embed+LN0 / weight-split prep -------------------------
#define WSPLIT_N  (NLAYER*4*EMBD*EMBD)          // 393216 = 3072*128
#define PREP_GRID (NTOK + WSPLIT_N/128)

__global__ void prep_kernel(const int* __restrict__ x_cat,
                            const float* __restrict__ x_num,
                            const float* __restrict__ x_eng,
                            const float* __restrict__ emb,
                            const float* __restrict__ emb_bias,
                            const float* __restrict__ emb_eng,
                            const float* __restrict__ emb_bias_eng,
                            const float* __restrict__ w,
                            const float* __restrict__ bb,
                            float* __restrict__ xout,
                            const float* __restrict__ Wqkv,
                            bf16* __restrict__ wqh, bf16* __restrict__ wql,
                            const float* __restrict__ Wo,
                            bf16* __restrict__ woh, bf16* __restrict__ wol)
{
    if (blockIdx.x >= NTOK) {
        int i = (blockIdx.x - NTOK)*128 + threadIdx.x;
        const int na = NLAYER*3*EMBD*EMBD;
        if (i < na) {
            float v = Wqkv[i];
            bf16 h = __float2bfloat16(v);
            wqh[i] = h;
            wql[i] = __float2bfloat16(v - __bfloat162float(h));
        } else {
            int j = i - na;
            float v = Wo[j];
            bf16 h = __float2bfloat16(v);
            woh[j] = h;
            wol[j] = __float2bfloat16(v - __bfloat162float(h));
        }
        return;
    }

    int tok = blockIdx.x;
    int b = tok / SEQ, t = tok % SEQ;
    int j = threadIdx.x;

    float v;
    if (t < 53) {
        int idx = x_cat[(b*51 + 50)*53 + t];
        v = emb[(size_t)idx*EMBD + j] + emb_bias[t*EMBD + j];
    } else if (t < 100) {
        int c = t - 53;
        v = emb[(size_t)(1306 + c)*EMBD + j] * x_num[(b*51 + 50)*47 + c]
            + emb_bias[t*EMBD + j];
    } else if (t < 200) {
        int c = t - 100;
        v = emb_eng[c*EMBD + j] * x_eng[b*100 + c] + emb_bias_eng[c*EMBD + j];
    } else {
        v = 0.f;
    }

    __shared__ float red[8];
    int lane = j & 31, warp = j >> 5;
    float s = v;
    #pragma unroll
    for (int o = 16; o; o >>= 1) s += __shfl_xor_sync(0xffffffffu, s, o);
    if (lane == 0) red[warp] = s;
    __syncthreads();
    float m = (red[0] + red[1] + red[2] + red[3]) * (1.f/128.f);
    float d = v - m;
    float s2 = d * d;
    #pragma unroll
    for (int o = 16; o; o >>= 1) s2 += __shfl_xor_sync(0xffffffffu, s2, o);
    if (lane == 0) red[4 + warp] = s2;
    __syncthreads();
    float var = (red[4] + red[5] + red[6] + red[7]) * (1.f/128.f);
    xout[(size_t)tok*EMBD + j] = d * rsqrtf(var + 1e-5f) * w[j] + bb[j];
}

__global__ void trans_split(const float* __restrict__ in, bf16* __restrict__ oh,
                            bf16* __restrict__ ol, int R, int C)
{
    __shared__ float tile[32][33];
    int mat = blockIdx.z;
    const float* src = in + (size_t)mat*R*C;
    int c0 = blockIdx.x*32, r0 = blockIdx.y*32;
    int x = threadIdx.x, y = threadIdx.y;
    #pragma unroll
    for (int i = 0; i < 32; i += 8)
        tile[y+i][x] = src[(size_t)(r0+y+i)*C + c0+x];
    __syncthreads();
    #pragma unroll
    for (int i = 0; i < 32; i += 8) {
        float v = tile[x][y+i];
        size_t idx = (size_t)mat*R*C + (size_t)(c0+y+i)*R + r0+x;
        bf16 h = __float2bfloat16(v);
        oh[idx] = h;
        ol[idx] = __float2bfloat16(v - __bfloat162float(h));
    }
}

// ---------------- warp-per-token LayerNorm -> bf16 hi/lo planes ---------------
__global__ void ln_warp_p(const float* __restrict__ src,
                          bf16* __restrict__ dh, bf16* __restrict__ dl,
                          const float* __restrict__ w, const float* __restrict__ bb,
                          int t0, int tstride)
{
    int lane = threadIdx.x & 31;
    int tokl = blockIdx.x * (blockDim.x >> 5) + (threadIdx.x >> 5);
    size_t tok = (size_t)t0 + (size_t)tokl * tstride;

    float4 v = *(const float4*)(src + tok*EMBD + lane*4);
    float s = v.x + v.y + v.z + v.w;
    #pragma unroll
    for (int o = 16; o; o >>= 1) s += __shfl_xor_sync(0xffffffffu, s, o);
    float m = s * (1.f/128.f);
    float dx = v.x-m, dy = v.y-m, dz = v.z-m, dw = v.w-m;
    float s2 = dx*dx + dy*dy + dz*dz + dw*dw;
    #pragma unroll
    for (int o = 16; o; o >>= 1) s2 += __shfl_xor_sync(0xffffffffu, s2, o);
    float inv = rsqrtf(s2 * (1.f/128.f) + 1e-5f);
    float4 wv = *(const float4*)(w + lane*4);
    float4 bv = *(const float4*)(bb + lane*4);
    float r0 = dx*inv*wv.x + bv.x, r1 = dy*inv*wv.y + bv.y;
    float r2 = dz*inv*wv.z + bv.z, r3 = dw*inv*wv.w + bv.w;
    uint32_t h0,l0,h1,l1;
    split2(r0, r1, h0, l0); split2(r2, r3, h1, l1);
    uint32_t* ph = (uint32_t*)(dh + tok*EMBD + lane*4);
    uint32_t* pl = (uint32_t*)(dl + tok*EMBD + lane*4);
    ph[0] = h0; ph[1] = h1; pl[0] = l0; pl[1] = l1;
}

// ---------------- fused LN2 + gate softmax -> planes --------------------------
__global__ void ln2g_p(const float* __restrict__ src,
                       bf16* __restrict__ dh, bf16* __restrict__ dl,
                       const float* __restrict__ w, const float* __restrict__ bb,
                       const float* __restrict__ Wg, const float* __restrict__ bg,
                       float* __restrict__ gate, int t0, int tstride)
{
    int lane = threadIdx.x & 31;
    int tokl = blockIdx.x * (blockDim.x >> 5) + (threadIdx.x >> 5);
    size_t tok = (size_t)t0 + (size_t)tokl * tstride;

    float4 v = *(const float4*)(src + tok*EMBD + lane*4);
    float s = v.x + v.y + v.z + v.w;
    #pragma unroll
    for (int o = 16; o; o >>= 1) s += __shfl_xor_sync(0xffffffffu, s, o);
    float m = s * (1.f/128.f);
    float dx = v.x-m, dy = v.y-m, dz = v.z-m, dw = v.w-m;
    float s2 = dx*dx + dy*dy + dz*dz + dw*dw;
    #pragma unroll
    for (int o = 16; o; o >>= 1) s2 += __shfl_xor_sync(0xffffffffu, s2, o);
    float inv = rsqrtf(s2 * (1.f/128.f) + 1e-5f);
    float4 wv = *(const float4*)(w + lane*4);
    float4 bv = *(const float4*)(bb + lane*4);
    float h[4];
    h[0] = dx*inv*wv.x + bv.x; h[1] = dy*inv*wv.y + bv.y;
    h[2] = dz*inv*wv.z + bv.z; h[3] = dw*inv*wv.w + bv.w;
    uint32_t hh0,ll0,hh1,ll1;
    split2(h[0], h[1], hh0, ll0); split2(h[2], h[3], hh1, ll1);
    uint32_t* ph = (uint32_t*)(dh + tok*EMBD + lane*4);
    uint32_t* pl = (uint32_t*)(dl + tok*EMBD + lane*4);
    ph[0] = hh0; ph[1] = hh1; pl[0] = ll0; pl[1] = ll1;

    float p[NEXP];
    #pragma unroll
    for (int e = 0; e < NEXP; e++) p[e] = 0.f;
    #pragma unroll
    for (int q = 0; q < 4; q++) {
        int j = lane*4 + q;
        #pragma unroll
        for (int e = 0; e < NEXP; e++) p[e] += h[q] * Wg[j*NEXP + e];
    }
    #pragma unroll
    for (int e = 0; e < NEXP; e++)
        #pragma unroll
        for (int o = 16; o; o >>= 1) p[e] += __shfl_xor_sync(0xffffffffu, p[e], o);
    if (lane == 0) {
        float mx = -1e30f;
        #pragma unroll
        for (int e = 0; e < NEXP; e++) { p[e] += bg[e]; mx = fmaxf(mx, p[e]); }
        float sum = 0.f;
        #pragma unroll
        for (int e = 0; e < NEXP; e++) { p[e] = __expf(p[e] - mx); sum += p[e]; }
        float is = 1.f / sum;
        #pragma unroll
        for (int e = 0; e < NEXP; e++) gate[tok*NEXP + e] = p[e] * is;
    }
}

// ---------------- bf16x3 GEMM: ldmatrix + 3-stage cp.async (R9 config) --------
#define GEMM_KP   24
#define GEMM_PL   (128*GEMM_KP)
#define GEMM_SMEM (4*3*GEMM_PL*2)   // 73728 bytes

template<int EPI>
__global__ void __launch_bounds__(256, 2)
gemm_p(const bf16* __restrict__ Ahp, const bf16* __restrict__ Alp, long rsA,
       const bf16* __restrict__ Bhp, const bf16* __restrict__ Blp,
       const float* __restrict__ bias,
       float* __restrict__ C, long rsC,
       bf16* __restrict__ Chp, bf16* __restrict__ Clp,
       const float* __restrict__ gate, long rsG,
       int K)
{
    constexpr int KP = GEMM_KP;
    constexpr int PL = GEMM_PL;
    extern __shared__ bf16 smg[];
    bf16* Ah = smg;
    bf16* Al = Ah + 3*PL;
    bf16* Bh = Al + 3*PL;
    bf16* Bl = Bh + 3*PL;

    const int tid  = threadIdx.x;
    const int warp = tid >> 5, lane = tid & 31;
    const int g = lane >> 2, r = lane & 3;
    const int wm = (warp & 3) * 32;
    const int wn = (warp >> 2) * 64;
    const int bx = blockIdx.x, by = blockIdx.y;

    float c[2][8][4];
    #pragma unroll
    for (int mi = 0; mi < 2; mi++)
        #pragma unroll
        for (int ni = 0; ni < 8; ni++)
            #pragma unroll
            for (int q = 0; q < 4; q++) c[mi][ni][q] = 0.f;

    const int crow = tid >> 1;
    const int ckseg = (tid & 1) << 3;
    const bf16* gAh = Ahp + (size_t)(by*128 + crow)*rsA + ckseg;
    const bf16* gAl = Alp + (size_t)(by*128 + crow)*rsA + ckseg;
    const bf16* gBh = Bhp + (size_t)(bx*128 + crow)*K + ckseg;
    const bf16* gBl = Blp + (size_t)(bx*128 + crow)*K + ckseg;

    uint32_t baseAh = (uint32_t)__cvta_generic_to_shared(Ah);
    uint32_t baseAl = (uint32_t)__cvta_generic_to_shared(Al);
    uint32_t baseBh = (uint32_t)__cvta_generic_to_shared(Bh);
    uint32_t baseBl = (uint32_t)__cvta_generic_to_shared(Bl);

    auto stage = [&](int k0, int s) {
        uint32_t off = (uint32_t)(s*PL + crow*KP + ckseg) * 2;
        CP_ASYNC16(baseAh + off, gAh + k0);
        CP_ASYNC16(baseAl + off, gAl + k0);
        CP_ASYNC16(baseBh + off, gBh + k0);
        CP_ASYNC16(baseBl + off, gBl + k0);
        asm volatile("cp.async.commit_group;" ::: "memory");
    };

    uint32_t a_off[2];
    #pragma unroll
    for (int mi = 0; mi < 2; mi++)
        a_off[mi] = (uint32_t)(((wm + mi*16 + (lane & 15))*KP + ((lane >> 4) << 3)) * 2);
    uint32_t b_off[4];
    #pragma unroll
    for (int p = 0; p < 4; p++)
        b_off[p] = (uint32_t)(((wn + p*16 + (lane & 7) + ((lane >> 4) << 3))*KP
                               + (((lane >> 3) & 1) << 3)) * 2);

    auto compute = [&](int s) {
        uint32_t so = (uint32_t)(s*PL*2);
        uint32_t ah[2][4], al[2][4];
        #pragma unroll
        for (int mi = 0; mi < 2; mi++) {
            LDSM_X4(ah[mi][0], ah[mi][1], ah[mi][2], ah[mi][3], baseAh + so + a_off[mi]);
            LDSM_X4(al[mi][0], al[mi][1], al[mi][2], al[mi][3], baseAl + so + a_off[mi]);
        }
        #pragma unroll
        for (int p = 0; p < 4; p++) {
            uint32_t bh[4], bl[4];
            LDSM_X4(bh[0], bh[1], bh[2], bh[3], baseBh + so + b_off[p]);
            LDSM_X4(bl[0], bl[1], bl[2], bl[3], baseBl + so + b_off[p]);
            MMA_BF16(c[0][2*p],   ah[0], bh[0], bh[1]);
            MMA_BF16(c[1][2*p],   ah[1], bh[0], bh[1]);
            MMA_BF16(c[0][2*p+1], ah[0], bh[2], bh[3]);
            MMA_BF16(c[1][2*p+1], ah[1], bh[2], bh[3]);
            MMA_BF16(c[0][2*p],   al[0], bh[0], bh[1]);
            MMA_BF16(c[1][2*p],   al[1], bh[0], bh[1]);
            MMA_BF16(c[0][2*p+1], al[0], bh[2], bh[3]);
            MMA_BF16(c[1][2*p+1], al[1], bh[2], bh[3]);
            MMA_BF16(c[0][2*p],   ah[0], bl[0], bl[1]);
            MMA_BF16(c[1][2*p],   ah[1], bl[0], bl[1]);
            MMA_BF16(c[0][2*p+1], ah[0], bl[2], bl[3]);
            MMA_BF16(c[1][2*p+1], ah[1], bl[2], bl[3]);
        }
    };

    const int nk = K >> 4;
    stage(0, 0);
    if (nk > 1) stage(16, 1);
    for (int it = 0; it < nk; ++it) {
        if (it + 1 < nk) asm volatile("cp.async.wait_group 1;" ::: "memory");
        else             asm volatile("cp.async.wait_group 0;" ::: "memory");
        __syncthreads();
        compute(it % 3);
        if (it + 2 < nk) stage((it + 2) << 4, (it + 2) % 3);
    }

    // ---------------- epilogue ----------------
    if (EPI == 4) {
        #pragma unroll
        for (int mi = 0; mi < 2; mi++)
            #pragma unroll
            for (int half = 0; half < 2; half++) {
                int m = by*128 + wm + mi*16 + g + half*8;
                float gg[NEXP];
                #pragma unroll
                for (int e = 0; e < NEXP; e++) gg[e] = gate[(size_t)m*rsG + e];
                float* crow2 = C + (size_t)m*rsC;
                #pragma unroll
                for (int ni = 0; ni < 8; ni++) {
                    int col = wn + ni*8 + 2*r;
                    float a0 = 0.f, a1 = 0.f;
                    #pragma unroll
                    for (int e = 0; e < NEXP; e++) {
                        a0 += gg[e] * bias[e*128 + col];
                        a1 += gg[e] * bias[e*128 + col + 1];
                    }
                    float2 old = *(float2*)(crow2 + col);
                    old.x += c[mi][ni][half*2 + 0] + a0;
                    old.y += c[mi][ni][half*2 + 1] + a1;
                    *(float2*)(crow2 + col) = old;
                }
            }
    } else if (EPI == 1) {
        #pragma unroll
        for (int mi = 0; mi < 2; mi++)
            #pragma unroll
            for (int half = 0; half < 2; half++) {
                int m = by*128 + wm + mi*16 + g + half*8;
                float gv = gate[(size_t)m*rsG + (bx >> 1)];
                #pragma unroll
                for (int ni = 0; ni < 8; ni++) {
                    int n = wn + ni*8 + 2*r;
                    float v0 = fmaxf(c[mi][ni][half*2+0] + bias[bx*128 + n],   0.f) * gv;
                    float v1 = fmaxf(c[mi][ni][half*2+1] + bias[bx*128 + n+1], 0.f) * gv;
                    uint32_t hi, lo;
                    split2(v0, v1, hi, lo);
                    *(uint32_t*)(Chp + (size_t)m*rsC + bx*128 + n) = hi;
                    *(uint32_t*)(Clp + (size_t)m*rsC + bx*128 + n) = lo;
                }
            }
    } else {
        #pragma unroll
        for (int mi = 0; mi < 2; mi++)
            #pragma unroll
            for (int half = 0; half < 2; half++) {
                int m = by*128 + wm + mi*16 + g + half*8;
                float* crow2 = C + (size_t)m*rsC + bx*128;
                const float* brow = bias + bx*128;
                #pragma unroll
                for (int ni = 0; ni < 8; ni++) {
                    int n = wn + ni*8 + 2*r;
                    float v0 = c[mi][ni][half*2 + 0] + brow[n];
                    float v1 = c[mi][ni][half*2 + 1] + brow[n+1];
                    if (EPI == 0) {
                        *(float2*)(crow2 + n) = make_float2(v0, v1);
                    } else {
                        float2 old = *(float2*)(crow2 + n);
                        old.x += v0; old.y += v1;
                        *(float2*)(crow2 + n) = old;
                    }
                }
            }
    }
}

// ---------------- streaming mma attention (P in registers) --------------------
// Warp owns 16 queries x all 208 keys. Max-free softmax => stream:
// O_unnorm += exp(S_chunk) @ V_chunk, rowsum += sum(exp); normalize at end.
// Score C-frags repacked in-register into A-frags for P@V (no smem P).
#define KSTR 40
#define VSTR 216
#define ATTN_SMEM ((208*KSTR + 32*VSTR)*2*2)   // 60928 bytes

__global__ void __launch_bounds__(256, 2)
attn_mma(const float* __restrict__ qkv, bf16* __restrict__ ohi, bf16* __restrict__ olo,
         int qt0)
{
    extern __shared__ char smraw[];
    bf16* Kh = (bf16*)smraw;                 // [208][KSTR]   ([key][d])
    bf16* Kl = Kh + 208*KSTR;
    bf16* Vh = Kl + 208*KSTR;                // [32][VSTR]    ([d][key])
    bf16* Vl = Vh + 32*VSTR;

    const int bh0_ = blockIdx.x, b = bh0_ >> 2, h = bh0_ & 3;
    const float* base = qkv + (size_t)b*SEQ*(3*EMBD) + h*HDIM;
    const int tid = threadIdx.x, warp = tid >> 5, lane = tid & 31;
    const int g = lane >> 2, r = lane & 3;
    const float scale = 0.1767766952966369f;   // 1/sqrt(32)

    uint32_t baseKh = (uint32_t)__cvta_generic_to_shared(Kh);
    uint32_t baseKl = (uint32_t)__cvta_generic_to_shared(Kl);
    uint32_t baseVh = (uint32_t)__cvta_generic_to_shared(Vh);
    uint32_t baseVl = (uint32_t)__cvta_generic_to_shared(Vl);

    for (int idx = tid; idx < 208*32; idx += 256) {
        int t = idx >> 5, d = idx & 31;
        float kv = 0.f, vv = 0.f;
        if (t < SEQ) {
            kv = base[(size_t)t*(3*EMBD) + EMBD   + d];
            vv = base[(size_t)t*(3*EMBD) + 2*EMBD + d];
        }
        bf16 khv = __float2bfloat16(kv);
        Kh[t*KSTR + d] = khv;
        Kl[t*KSTR + d] = __float2bfloat16(kv - __bfloat162float(khv));
        bf16 vhv = __float2bfloat16(vv);
        Vh[d*VSTR + t] = vhv;
        Vl[d*VSTR + t] = __float2bfloat16(vv - __bfloat162float(vhv));
    }
    __syncthreads();

    const uint32_t kofl = (uint32_t)((((lane & 7))*KSTR + (((lane >> 3) & 3) << 3)) * 2);
    const uint32_t vofl = (uint32_t)((((lane & 7))*VSTR + (((lane >> 3) & 1) << 3)) * 2);

    // q-tiles of 16: tiles qt0+warp, +8 ... (< 13)
    for (int t = qt0 + warp; t < 13; t += 8) {
        const int qbase = t*16;

        // Q fragments (scale folded, hi/lo split); j: row +(j&1)*8, col +(j>>1)*8
        uint32_t qh[2][4], ql[2][4];
        #pragma unroll
        for (int ks = 0; ks < 2; ks++)
            #pragma unroll
            for (int j = 0; j < 4; j++) {
                int qq = qbase + g + ((j & 1) << 3);
                if (qq > 200) qq = 200;
                int kk = ks*16 + 2*r + ((j >> 1) << 3);
                float2 v = *(const float2*)(base + (size_t)qq*(3*EMBD) + kk);
                split2(v.x*scale, v.y*scale, qh[ks][j], ql[ks][j]);
            }

        float oc[4][4];
        #pragma unroll
        for (int ni = 0; ni < 4; ni++)
            #pragma unroll
            for (int q = 0; q < 4; q++) oc[ni][q] = 0.f;
        float osum0 = 0.f, osum1 = 0.f;

        for (int kt = 0; kt < 13; kt++) {
            // ---- scores for 16 keys (2 n8 tiles)
            float s[2][4];
            #pragma unroll
            for (int p = 0; p < 2; p++) {
                s[p][0] = s[p][1] = s[p][2] = s[p][3] = 0.f;
                uint32_t ko = (uint32_t)((kt*16 + p*8)*KSTR*2) + kofl;
                uint32_t kb[4], klv[4];
                LDSM_X4(kb[0], kb[1], kb[2], kb[3], baseKh + ko);
                LDSM_X4(klv[0], klv[1], klv[2], klv[3], baseKl + ko);
                MMA_BF16(s[p], qh[0], kb[0], kb[1]);
                MMA_BF16(s[p], ql[0], kb[0], kb[1]);
                MMA_BF16(s[p], qh[0], klv[0], klv[1]);
                MMA_BF16(s[p], qh[1], kb[2], kb[3]);
                MMA_BF16(s[p], ql[1], kb[2], kb[3]);
                MMA_BF16(s[p], qh[1], klv[2], klv[3]);
            }
            // ---- exp + key mask + row sums (max-free softmax)
            #pragma unroll
            for (int p = 0; p < 2; p++) {
                int c0 = kt*16 + p*8 + 2*r;
                float e0 = (c0     <= 200) ? __expf(s[p][0]) : 0.f;
                float e1 = (c0 + 1 <= 200) ? __expf(s[p][1]) : 0.f;
                float e2 = (c0     <= 200) ? __expf(s[p][2]) : 0.f;
                float e3 = (c0 + 1 <= 200) ? __expf(s[p][3]) : 0.f;
                s[p][0] = e0; s[p][1] = e1; s[p][2] = e2; s[p][3] = e3;
                osum0 += e0 + e1;
                osum1 += e2 + e3;
            }
            // ---- repack C-frags -> A-frags (rows g,g+8; k = kt*16..+15)
            uint32_t pah[4], pal[4];
            split2(s[0][0], s[0][1], pah[0], pal[0]);
            split2(s[0][2], s[0][3], pah[1], pal[1]);
            split2(s[1][0], s[1][1], pah[2], pal[2]);
            split2(s[1][2], s[1][3], pah[3], pal[3]);
            // ---- O += P @ V (4 d-tiles)
            #pragma unroll
            for (int ni = 0; ni < 4; ni++) {
                uint32_t vo = (uint32_t)((ni*8*VSTR + kt*16)*2) + vofl;
                uint32_t vh0, vh1, vl0, vl1;
                LDSM_X2(vh0, vh1, baseVh + vo);
                LDSM_X2(vl0, vl1, baseVl + vo);
                MMA_BF16(oc[ni], pah, vh0, vh1);
                MMA_BF16(oc[ni], pal, vh0, vh1);
                MMA_BF16(oc[ni], pah, vl0, vl1);
            }
        }

        // ---- row sums across the 4 r-lanes, normalize, write planes
        osum0 += __shfl_xor_sync(0xffffffffu, osum0, 1);
        osum0 += __shfl_xor_sync(0xffffffffu, osum0, 2);
        osum1 += __shfl_xor_sync(0xffffffffu, osum1, 1);
        osum1 += __shfl_xor_sync(0xffffffffu, osum1, 2);
        float inv0 = 1.f / osum0, inv1 = 1.f / osum1;

        int q0r = qbase + g, q1r = qbase + g + 8;
        #pragma unroll
        for (int ni = 0; ni < 4; ni++) {
            int d = ni*8 + 2*r;
            if (q0r <= 200) {
                uint32_t hi, lo;
                split2(oc[ni][0]*inv0, oc[ni][1]*inv0, hi, lo);
                size_t off = ((size_t)b*SEQ + q0r)*EMBD + h*HDIM + d;
                *(uint32_t*)(ohi + off) = hi;
                *(uint32_t*)(olo + off) = lo;
            }
            if (q1r <= 200) {
                uint32_t hi, lo;
                split2(oc[ni][2]*inv1, oc[ni][3]*inv1, hi, lo);
                size_t off = ((size_t)b*SEQ + q1r)*EMBD + h*HDIM + d;
                *(uint32_t*)(ohi + off) = hi;
                *(uint32_t*)(olo + off) = lo;
            }
        }
    }
}

// ---------------- output copy -------------------------------------------------
__global__ void copy_out_kernel(const float* __restrict__ x, float* __restrict__ out)
{
    int b = blockIdx.x, j = threadIdx.x;
    out[b*EMBD + j] = x[((size_t)b*SEQ + 200)*EMBD + j];
}

// ---------------- launcher ----------------------------------------------------
extern "C" void kernel_launch(void* const* d_in, const int* in_sizes, int n_in,
                              void* d_out, int out_size)
{
    (void)in_sizes; (void)n_in; (void)out_size;

    const int*   x_cat        = (const int*)  d_in[0];
    const float* x_num        = (const float*)d_in[1];
    const float* x_eng        = (const float*)d_in[2];
    const float* emb          = (const float*)d_in[3];
    const float* emb_bias     = (const float*)d_in[4];
    const float* emb_eng      = (const float*)d_in[5];
    const float* emb_bias_eng = (const float*)d_in[6];
    const float* ln0_w        = (const float*)d_in[7];
    const float* ln0_b        = (const float*)d_in[8];
    const float* ln1_w        = (const float*)d_in[9];
    const float* ln1_b        = (const float*)d_in[10];
    const float* Wqkv         = (const float*)d_in[11];
    const float* bqkv         = (const float*)d_in[12];
    const float* Wo           = (const float*)d_in[13];
    const float* bo           = (const float*)d_in[14];
    const float* ln2_w        = (const float*)d_in[15];
    const float* ln2_b        = (const float*)d_in[16];
    const float* Wg           = (const float*)d_in[17];
    const float* bg           = (const float*)d_in[18];
    const float* W1           = (const float*)d_in[19];
    const float* b1           = (const float*)d_in[20];
    const float* W2           = (const float*)d_in[21];
    const float* b2           = (const float*)d_in[22];
    float* out = (float*)d_out;

    float *px, *pqkv, *pgate;
    bf16 *phh, *phl, *poh, *pol, *phidh, *phidl;
    bf16 *pwqkvh, *pwqkvl, *pwoh, *pwol, *pw1h, *pw1l, *pw2h, *pw2l;
    cudaGetSymbolAddress((void**)&px,    g_x);
    cudaGetSymbolAddress((void**)&pqkv,  g_qkv);
    cudaGetSymbolAddress((void**)&pgate, g_gate);
    cudaGetSymbolAddress((void**)&phh,   g_hh);
    cudaGetSymbolAddress((void**)&phl,   g_hl);
    cudaGetSymbolAddress((void**)&poh,   g_oh);
    cudaGetSymbolAddress((void**)&pol,   g_ol);
    cudaGetSymbolAddress((void**)&phidh, g_hidh);
    cudaGetSymbolAddress((void**)&phidl, g_hidl);
    cudaGetSymbolAddress((void**)&pwqkvh, g_wqkvh);
    cudaGetSymbolAddress((void**)&pwqkvl, g_wqkvl);
    cudaGetSymbolAddress((void**)&pwoh,   g_woh);
    cudaGetSymbolAddress((void**)&pwol,   g_wol);
    cudaGetSymbolAddress((void**)&pw1h,   g_w1h);
    cudaGetSymbolAddress((void**)&pw1l,   g_w1l);
    cudaGetSymbolAddress((void**)&pw2h,   g_w2h);
    cudaGetSymbolAddress((void**)&pw2l,   g_w2l);

    cudaFuncSetAttribute(attn_mma, cudaFuncAttributeMaxDynamicSharedMemorySize, ATTN_SMEM);
    cudaFuncSetAttribute(gemm_p<0>, cudaFuncAttributeMaxDynamicSharedMemorySize, GEMM_SMEM);
    cudaFuncSetAttribute(gemm_p<1>, cudaFuncAttributeMaxDynamicSharedMemorySize, GEMM_SMEM);
    cudaFuncSetAttribute(gemm_p<3>, cudaFuncAttributeMaxDynamicSharedMemorySize, GEMM_SMEM);
    cudaFuncSetAttribute(gemm_p<4>, cudaFuncAttributeMaxDynamicSharedMemorySize, GEMM_SMEM);

    // launch order: #4 (ncu capture slot) = layer-0 attention
    prep_kernel<<<PREP_GRID, 128>>>(x_cat, x_num, x_eng, emb, emb_bias,
                                    emb_eng, emb_bias_eng, ln0_w, ln0_b, px,
                                    Wqkv, pwqkvh, pwqkvl, Wo, pwoh, pwol);       // 1
    ln_warp_p<<<NTOK/8, 256>>>(px, phh, phl, ln1_w, ln1_b, 0, 1);                // 2
    gemm_p<0><<<dim3(3, NTOK/128), 256, GEMM_SMEM>>>(phh, phl, EMBD,
                                              pwqkvh, pwqkvl, bqkv,
                                              pqkv, 3*EMBD, nullptr, nullptr,
                                              nullptr, 0, EMBD);                 // 3
    attn_mma<<<BATCH*NHEAD, 256, ATTN_SMEM>>>(pqkv, poh, pol, 0);                // 4 (profiled)
    trans_split<<<dim3(FFD/32, EMBD/32, NLAYER*NEXP), dim3(32,8)>>>(W1, pw1h, pw1l, EMBD, FFD);
    trans_split<<<dim3(EMBD/32, (NEXP*FFD)/32, NLAYER), dim3(32,8)>>>(W2, pw2h, pw2l, NEXP*FFD, EMBD);

    for (int i = 0; i < NLAYER; i++) {
        const bf16* wqh = pwqkvh + (size_t)i*3*EMBD*EMBD;
        const bf16* wql = pwqkvl + (size_t)i*3*EMBD*EMBD;
        const float* bqkv_i = bqkv + (size_t)i*3*EMBD;
        const bf16* woh = pwoh + (size_t)i*EMBD*EMBD;
        const bf16* wol = pwol + (size_t)i*EMBD*EMBD;
        const float* bo_i = bo + (size_t)i*EMBD;
        const float* wg_i = Wg + (size_t)i*EMBD*NEXP;
        const float* bg_i = bg + (size_t)i*NEXP;
        const bf16* w1h = pw1h + (size_t)i*NEXP*FFD*EMBD;
        const bf16* w1l = pw1l + (size_t)i*NEXP*FFD*EMBD;
        const float* b1_i = b1 + (size_t)i*NEXP*FFD;
        const bf16* w2h = pw2h + (size_t)i*EMBD*NEXP*FFD;
        const bf16* w2l = pw2l + (size_t)i*EMBD*NEXP*FFD;
        const float* b2_i = b2 + (size_t)i*NEXP*EMBD;

        if (i > 0) {
            ln_warp_p<<<NTOK/8, 256>>>(px, phh, phl, ln1_w + i*EMBD, ln1_b + i*EMBD, 0, 1);
            gemm_p<0><<<dim3(3, NTOK/128), 256, GEMM_SMEM>>>(phh, phl, EMBD, wqh, wql, bqkv_i,
                                                  pqkv, 3*EMBD, nullptr, nullptr,
                                                  nullptr, 0, EMBD);
            int qt0 = (i == NLAYER-1) ? 12 : 0;
            attn_mma<<<BATCH*NHEAD, 256, ATTN_SMEM>>>(pqkv, poh, pol, qt0);
        }

        if (i < NLAYER-1) {
            gemm_p<3><<<dim3(1, NTOK/128), 256, GEMM_SMEM>>>(poh, pol, EMBD, woh, wol, bo_i,
                                                  px, EMBD, nullptr, nullptr,
                                                  nullptr, 0, EMBD);
            ln2g_p<<<NTOK/8, 256>>>(px, phh, phl, ln2_w + i*EMBD, ln2_b + i*EMBD,
                                    wg_i, bg_i, pgate, 0, 1);
            gemm_p<1><<<dim3(10, NTOK/128), 256, GEMM_SMEM>>>(phh, phl, EMBD, w1h, w1l, b1_i,
                                                   nullptr, NEXP*FFD, phidh, phidl,
                                                   pgate, NEXP, EMBD);
            gemm_p<4><<<dim3(1, NTOK/128), 256, GEMM_SMEM>>>(phidh, phidl, NEXP*FFD, w2h, w2l, b2_i,
                                                  px, EMBD, nullptr, nullptr,
                                                  pgate, NEXP, NEXP*FFD);
        } else {
            const long rs = (long)SEQ*EMBD;
            gemm_p<3><<<dim3(1, BATCH/128), 256, GEMM_SMEM>>>(poh + (size_t)200*EMBD, pol + (size_t)200*EMBD, rs,
                                                   woh, wol, bo_i,
                                                   px + (size_t)200*EMBD, rs, nullptr, nullptr,
                                                   nullptr, 0, EMBD);
            ln2g_p<<<BATCH/8, 256>>>(px, phh, phl, ln2_w + i*EMBD, ln2_b + i*EMBD,
                                     wg_i, bg_i, pgate, 200, SEQ);
            gemm_p<1><<<dim3(10, BATCH/128), 256, GEMM_SMEM>>>(phh + (size_t)200*EMBD, phl + (size_t)200*EMBD, rs,
                                                    w1h, w1l, b1_i,
                                                    nullptr, NEXP*FFD, phidh, phidl,
                                                    pgate + (size_t)200*NEXP, (long)SEQ*NEXP, EMBD);
            gemm_p<4><<<dim3(1, BATCH/128), 256, GEMM_SMEM>>>(phidh, phidl, NEXP*FFD, w2h, w2l, b2_i,
                                                   px + (size_t)200*EMBD, rs, nullptr, nullptr,
                                                   pgate + (size_t)200*NEXP, (long)SEQ*NEXP,
                                                   NEXP*FFD);
        }
    }

    copy_out_kernel<<<BATCH, 128>>>(px, out);
}